// round 9
// baseline (speedup 1.0000x reference)
#include <cuda_runtime.h>
#include <cuda_bf16.h>
#include <math.h>

#define Bq   2
#define Lq   1024
#define Hq   16
#define Dq   64
#define HIDq 1024

typedef __nv_bfloat16 bf16;
typedef unsigned long long ull;

// ---------------- scratch (static device globals; no runtime alloc) ----------
__device__ float g_qkv[Bq * Lq * 3 * Hq * Dq];                  // (B,L,3,H,D)
__device__ float g_sc[(long long)Bq * Hq * Lq * Lq];            // (B,H,L,L) fp32 scores

__device__ bf16 g_qhi[Bq * Hq * Lq * Dq], g_qlo[Bq * Hq * Lq * Dq];   // (B,H,L,D)
__device__ bf16 g_khi[Bq * Hq * Lq * Dq], g_klo[Bq * Hq * Lq * Dq];
__device__ bf16 g_vThi[Bq * Hq * Dq * Lq], g_vTlo[Bq * Hq * Dq * Lq]; // (B,H,D,L)
__device__ bf16 g_whi[(long long)Bq * Hq * Lq * Lq];                  // weights hi
__device__ bf16 g_wlo[(long long)Bq * Hq * Lq * Lq];                  // weights lo

__device__ bf16 g_xhi[2048 * 1024], g_xlo[2048 * 1024];
__device__ bf16 g_wqkvT_hi[3072 * 1024], g_wqkvT_lo[3072 * 1024];
__device__ bf16 g_attnhi[2048 * 1024], g_attnlo[2048 * 1024];   // (B,L,H*D)
__device__ bf16 g_woT_hi[1024 * 1024], g_woT_lo[1024 * 1024];

// DAPE precomputed tables
__device__ float g_kc[32 * 1024];     // [o][dist]
__device__ float g_ktab[16 * 1024];   // [h][dist]

// ---------------- f32x2 packed helpers ---------------------------------------
__device__ __forceinline__ ull pk2(float lo, float hi) {
    ull r; asm("mov.b64 %0,{%1,%2};" : "=l"(r) : "f"(lo), "f"(hi)); return r;
}
__device__ __forceinline__ void upk2(ull v, float& lo, float& hi) {
    asm("mov.b64 {%0,%1},%2;" : "=f"(lo), "=f"(hi) : "l"(v));
}
__device__ __forceinline__ ull ffma2(ull a, ull b, ull c) {
    ull d; asm("fma.rn.f32x2 %0,%1,%2,%3;" : "=l"(d) : "l"(a), "l"(b), "l"(c));
    return d;
}

// ======================= split-bf16 tensor-core GEMM ========================
#define BM 128
#define BK 32
#define NSTG 3

__device__ __forceinline__ void ldm_x4(unsigned r[4], unsigned addr) {
    asm volatile("ldmatrix.sync.aligned.m8n8.x4.shared.b16 {%0,%1,%2,%3}, [%4];"
        : "=r"(r[0]), "=r"(r[1]), "=r"(r[2]), "=r"(r[3]) : "r"(addr));
}
__device__ __forceinline__ void mma16816(float c[4], const unsigned a[4],
                                         unsigned b0, unsigned b1) {
    asm volatile("mma.sync.aligned.m16n8k16.row.col.f32.bf16.bf16.f32 "
        "{%0,%1,%2,%3},{%4,%5,%6,%7},{%8,%9},{%0,%1,%2,%3};"
        : "+f"(c[0]), "+f"(c[1]), "+f"(c[2]), "+f"(c[3])
        : "r"(a[0]), "r"(a[1]), "r"(a[2]), "r"(a[3]), "r"(b0), "r"(b1));
}
__device__ __forceinline__ void cp16(unsigned saddr, const void* g) {
    asm volatile("cp.async.cg.shared.global [%0], [%1], 16;\n" :: "r"(saddr), "l"(g));
}

// C = alpha * A(M,K) x B(N,K)^T, split precision hh+hl+lh.
template <int BN_, int CJ, int CK, int OUT>
__global__ __launch_bounds__(256)
void hgemm_kernel(const bf16* __restrict__ Ahi, const bf16* __restrict__ Alo,
                  const bf16* __restrict__ Bhi, const bf16* __restrict__ Blo,
                  float* __restrict__ Cf, bf16* __restrict__ Chi, bf16* __restrict__ Clo,
                  int M, int N, int K, int lda, int ldb, int ldc,
                  long long sA, long long sB, long long sC, float alpha)
{
    constexpr int WCOL = BN_ / 4;
    constexpr int NT = WCOL / 16;
    constexpr unsigned BOFF = 16384u;
    constexpr unsigned BLO  = 16384u + BN_ * 64u;
    constexpr unsigned STG  = 16384u + BN_ * 128u;

    const int bz = blockIdx.z;
    Ahi += (long long)bz * sA;  Alo += (long long)bz * sA;
    Bhi += (long long)bz * sB;  Blo += (long long)bz * sB;

    const int bi = blockIdx.y * BM, bj = blockIdx.x * BN_;
    if (CJ && bj > bi + BM - 1) return;

    extern __shared__ bf16 smem[];
    const unsigned sgen = (unsigned)__cvta_generic_to_shared(smem);
    const int tid = threadIdx.x;
    const int wid = tid >> 5, lane = tid & 31;
    const int wm = wid >> 2, wn = wid & 3;

    float acc[4][2 * NT][4];
    #pragma unroll
    for (int a = 0; a < 4; a++)
        #pragma unroll
        for (int b = 0; b < 2 * NT; b++)
            #pragma unroll
            for (int c = 0; c < 4; c++) acc[a][b][c] = 0.f;

    const int kmax = CK ? (bi + BM < K ? bi + BM : K) : K;
    const int nkt = kmax / BK;

    auto load_stage = [&](int stage, int kt) {
        int k0 = kt * BK;
        unsigned sb = sgen + stage * STG;
        #pragma unroll
        for (int rep = 0; rep < 2; rep++) {
            int c = tid + rep * 256;
            int row = c >> 2, kc = c & 3;
            unsigned swc = (unsigned)(kc ^ ((row >> 1) & 3));
            unsigned so = sb + (unsigned)row * 64u + swc * 16u;
            cp16(so,         Ahi + (size_t)(bi + row) * lda + k0 + kc * 8);
            cp16(so + 8192u, Alo + (size_t)(bi + row) * lda + k0 + kc * 8);
        }
        #pragma unroll
        for (int rep = 0; rep < BN_ / 64; rep++) {
            int c = tid + rep * 256;
            int row = c >> 2, kc = c & 3;
            unsigned swc = (unsigned)(kc ^ ((row >> 1) & 3));
            unsigned so = sb + (unsigned)row * 64u + swc * 16u;
            cp16(so + BOFF, Bhi + (size_t)(bj + row) * ldb + k0 + kc * 8);
            cp16(so + BLO,  Blo + (size_t)(bj + row) * ldb + k0 + kc * 8);
        }
    };

    auto compute_stage = [&](int stage) {
        unsigned sb = sgen + stage * STG;
        #pragma unroll
        for (int ks = 0; ks < 2; ks++) {
            int r = lane & 15;
            int cc = ks * 2 + (lane >> 4);
            unsigned a_hi[4][4], a_lo[4][4];
            #pragma unroll
            for (int mt = 0; mt < 4; mt++) {
                int row = wm * 64 + mt * 16 + r;
                unsigned swc = (unsigned)(cc ^ ((row >> 1) & 3));
                unsigned addr = sb + (unsigned)row * 64u + swc * 16u;
                ldm_x4(a_hi[mt], addr);
                ldm_x4(a_lo[mt], addr + 8192u);
            }
            unsigned b_hi[NT][4], b_lo[NT][4];
            #pragma unroll
            for (int bt = 0; bt < NT; bt++) {
                int row = wn * WCOL + bt * 16 + r;
                unsigned swc = (unsigned)(cc ^ ((row >> 1) & 3));
                unsigned addr = sb + BOFF + (unsigned)row * 64u + swc * 16u;
                ldm_x4(b_hi[bt], addr);
                ldm_x4(b_lo[bt], addr + (BN_ * 64u));
            }
            #pragma unroll
            for (int mt = 0; mt < 4; mt++)
                #pragma unroll
                for (int n = 0; n < 2 * NT; n++) {
                    int bt = n >> 1, sel = n & 1;
                    unsigned b0h = b_hi[bt][sel], b1h = b_hi[bt][sel + 2];
                    unsigned b0l = b_lo[bt][sel], b1l = b_lo[bt][sel + 2];
                    mma16816(acc[mt][n], a_hi[mt], b0h, b1h);
                    mma16816(acc[mt][n], a_hi[mt], b0l, b1l);
                    mma16816(acc[mt][n], a_lo[mt], b0h, b1h);
                }
        }
    };

    #pragma unroll
    for (int s = 0; s < NSTG - 1; s++) {
        if (s < nkt) load_stage(s, s);
        asm volatile("cp.async.commit_group;\n");
    }
    for (int kt = 0; kt < nkt; kt++) {
        asm volatile("cp.async.wait_group %0;\n" :: "n"(NSTG - 2));
        __syncthreads();
        int kn = kt + NSTG - 1;
        if (kn < nkt) load_stage(kn % NSTG, kn);
        asm volatile("cp.async.commit_group;\n");
        compute_stage(kt % NSTG);
    }

    #pragma unroll
    for (int mt = 0; mt < 4; mt++) {
        int r0 = bi + wm * 64 + mt * 16 + (lane >> 2);
        #pragma unroll
        for (int n = 0; n < 2 * NT; n++) {
            int col = bj + wn * WCOL + (n >> 1) * 16 + (n & 1) * 8 + 2 * (lane & 3);
            if (OUT == 0) {
                float* C = Cf + (long long)bz * sC;
                float2 v0 = {alpha * acc[mt][n][0], alpha * acc[mt][n][1]};
                float2 v1 = {alpha * acc[mt][n][2], alpha * acc[mt][n][3]};
                *(float2*)&C[(size_t)r0 * ldc + col] = v0;
                *(float2*)&C[(size_t)(r0 + 8) * ldc + col] = v1;
            } else {
                long long base = (long long)(bz >> 4) * ((long long)Lq * HIDq)
                               + (long long)(bz & 15) * Dq;
                #pragma unroll
                for (int rr = 0; rr < 2; rr++) {
                    float va = acc[mt][n][rr * 2], vb = acc[mt][n][rr * 2 + 1];
                    bf16 ha = __float2bfloat16(va), hb = __float2bfloat16(vb);
                    bf16 la = __float2bfloat16(va - __bfloat162float(ha));
                    bf16 lb = __float2bfloat16(vb - __bfloat162float(hb));
                    size_t off = base + (size_t)(r0 + rr * 8) * ldc + col;
                    *(__nv_bfloat162*)&Chi[off] = __nv_bfloat162(ha, hb);
                    *(__nv_bfloat162*)&Clo[off] = __nv_bfloat162(la, lb);
                }
            }
        }
    }
}

// ---------------- fp32 -> bf16 hi/lo conversion kernels ----------------------
__global__ void conv_split_kernel(const float* __restrict__ src,
                                  bf16* __restrict__ hi, bf16* __restrict__ lo, int n)
{
    int i = blockIdx.x * blockDim.x + threadIdx.x;
    if (i >= n) return;
    float v = src[i];
    bf16 h = __float2bfloat16(v);
    hi[i] = h;
    lo[i] = __float2bfloat16(v - __bfloat162float(h));
}

__global__ void conv_split_trans_kernel(const float* __restrict__ W,
                                        bf16* __restrict__ hi, bf16* __restrict__ lo,
                                        int K, int N)
{
    __shared__ float t[32][33];
    int k0 = blockIdx.y * 32, n0 = blockIdx.x * 32;
    int tx = threadIdx.x, ty = threadIdx.y;
    #pragma unroll
    for (int r = ty; r < 32; r += 8)
        t[r][tx] = W[(size_t)(k0 + r) * N + n0 + tx];
    __syncthreads();
    #pragma unroll
    for (int r = ty; r < 32; r += 8) {
        float v = t[tx][r];
        bf16 h = __float2bfloat16(v);
        hi[(size_t)(n0 + r) * K + k0 + tx] = h;
        lo[(size_t)(n0 + r) * K + k0 + tx] = __float2bfloat16(v - __bfloat162float(h));
    }
}

// ---------------- qkv split + RoPE -> bf16 hi/lo (q,k) + transposed v -------
__global__ __launch_bounds__(256)
void rope_split_kernel(const float* __restrict__ qkv,
                       bf16* __restrict__ qhi, bf16* __restrict__ qlo,
                       bf16* __restrict__ khi, bf16* __restrict__ klo,
                       bf16* __restrict__ vThi, bf16* __restrict__ vTlo)
{
    __shared__ float sv[32][65];
    int bid = blockIdx.x;
    int l0 = (bid & 31) * 32;
    int h = (bid >> 5) & 15;
    int b = bid >> 9;
    int tid = threadIdx.x;

    #pragma unroll
    for (int e = 0; e < 8; e++) {
        int idx = tid + e * 256;
        int d = idx & 63, lr = idx >> 6;
        int l = l0 + lr;
        long long base = ((long long)(b * Lq + l) * 3) * (Hq * Dq) + h * Dq;
        float qa = qkv[base + d];
        float ka = qkv[base + Hq * Dq + d];
        float vv = qkv[base + 2 * Hq * Dq + d];
        int dp = (d < 32) ? d + 32 : d - 32;
        float qb = qkv[base + dp];
        float kb = qkv[base + Hq * Dq + dp];

        int fi = (d < 32) ? d : d - 32;
        float ang = (float)l * powf(10000.0f, -(float)fi / 32.0f);
        float c = cosf(ang), s = sinf(ang);
        float sgn = (d < 32) ? -1.0f : 1.0f;

        float qv = qa * c + sgn * qb * s;
        float kv = ka * c + sgn * kb * s;

        long long o = ((long long)(b * Hq + h) * Lq + l) * Dq + d;
        bf16 qh = __float2bfloat16(qv), kh = __float2bfloat16(kv);
        qhi[o] = qh; qlo[o] = __float2bfloat16(qv - __bfloat162float(qh));
        khi[o] = kh; klo[o] = __float2bfloat16(kv - __bfloat162float(kh));
        sv[lr][d] = vv;
    }
    __syncthreads();
    #pragma unroll
    for (int e = 0; e < 8; e++) {
        int idx = tid + e * 256;
        int lr = idx & 31, d = idx >> 5;
        float vv = sv[lr][d];
        bf16 vh = __float2bfloat16(vv);
        long long o = ((long long)(b * Hq + h) * Dq + d) * Lq + l0 + lr;
        vThi[o] = vh;
        vTlo[o] = __float2bfloat16(vv - __bfloat162float(vh));
    }
}

// ---------------- DAPE tables: kc[o][dist], ktab[h][dist] --------------------
__global__ void dape_pre_kernel(const float* __restrict__ w1, const float* __restrict__ b1,
                                const float* __restrict__ log_p, const float* __restrict__ log_a,
                                float* __restrict__ kc_t, float* __restrict__ ktab_t)
{
    int dist = blockIdx.x;
    int t = threadIdx.x;    // 32
    __shared__ float kv[16];
    if (t < 16) {
        float p = log1pf(expf(log_p[t]));
        float a = log1pf(expf(log_a[t]));
        float kvv = -p * log1pf(a * (float)dist);
        kv[t] = kvv;
        ktab_t[t * 1024 + dist] = kvv;
    }
    __syncthreads();
    float acc = b1[t];
    #pragma unroll
    for (int h = 0; h < 16; h++) acc += kv[h] * w1[(16 + h) * 32 + t];
    kc_t[t * 1024 + dist] = acc;
}

// ---- fused DAPE MLP + kerple + causal softmax (f32x2, wedge-paired) --------
// One block per (b, pair): rows i1=ih and i2=1023-ih. 1024 threads.
// thread t<=i1 -> (i1, j=t); t>i1 -> (i2, j=t-i1-1); thread i1 also does (i2,i2)
// via smem side-channel. Every thread writes one zero element of the upper
// triangles so the full L x L weight planes are defined.
__global__ __launch_bounds__(1024, 1)
void dape_softmax_kernel(const float* __restrict__ scores,
                         bf16* __restrict__ whi, bf16* __restrict__ wlo,
                         const float* __restrict__ w1, const float* __restrict__ w2,
                         const float* __restrict__ b2,
                         const float* __restrict__ kc_t, const float* __restrict__ ktab_t)
{
    __shared__ ull s_w1p[256];
    __shared__ ull s_w2p[256];
    __shared__ float s_b2[16];
    __shared__ float s_red[32 * 32];   // [row16+h][warp]
    __shared__ float s_mx[32];
    __shared__ float s_inv[32];
    __shared__ float s_diag[16];
    __shared__ float s_dexp[16];

    const int tid = threadIdx.x;
    const int ih = blockIdx.x & 511;
    const int b = blockIdx.x >> 9;
    const int i1 = ih, i2 = 1023 - ih;

    if (tid < 256) {
        int o = tid >> 3, p = tid & 7;
        s_w1p[o * 8 + p] = pk2(w1[(2 * p) * 32 + o], w1[(2 * p + 1) * 32 + o]);
        s_w2p[o * 8 + p] = pk2(w2[o * 16 + 2 * p], w2[o * 16 + 2 * p + 1]);
    }
    if (tid < 16) s_b2[tid] = b2[tid];
    __syncthreads();

    const bool r1 = (tid <= i1);
    const int row = r1 ? i1 : i2;
    const int col = r1 ? tid : tid - i1 - 1;
    const int dist = r1 ? (i1 - tid) : (1024 - tid);
    const long long bb = (long long)b * (Hq * Lq * Lq);

    auto mlp = [&](int rr, int jj, int dd, ull* o2) {
        long long rb = bb + (long long)rr * Lq;
        ull s2[8];
        #pragma unroll
        for (int p = 0; p < 8; p++) {
            float s0 = scores[rb + (long long)(2 * p)     * (Lq * Lq) + jj];
            float s1 = scores[rb + (long long)(2 * p + 1) * (Lq * Lq) + jj];
            s2[p] = pk2(s0, s1);
            o2[p] = pk2(s0 + ktab_t[(2 * p) * 1024 + dd] + s_b2[2 * p],
                        s1 + ktab_t[(2 * p + 1) * 1024 + dd] + s_b2[2 * p + 1]);
        }
        #pragma unroll 4
        for (int o = 0; o < 32; o++) {
            ull acc2 = pk2(kc_t[o * 1024 + dd], 0.0f);
            #pragma unroll
            for (int p = 0; p < 8; p++) acc2 = ffma2(s2[p], s_w1p[o * 8 + p], acc2);
            float a0, a1; upk2(acc2, a0, a1);
            float acc = a0 + a1;
            float u = 0.7978845608f * (acc + 0.044715f * acc * acc * acc);
            float th; asm("tanh.approx.f32 %0,%1;" : "=f"(th) : "f"(u));
            float g = 0.5f * acc * (1.0f + th);
            ull g2 = pk2(g, g);
            #pragma unroll
            for (int p = 0; p < 8; p++) o2[p] = ffma2(g2, s_w2p[o * 8 + p], o2[p]);
        }
    };

    ull out2[8];
    if (tid == i1) {                     // leftover diagonal (i2, i2), dist 0
        mlp(i2, i2, 0, out2);
        #pragma unroll
        for (int p = 0; p < 8; p++) {
            float v0, v1; upk2(out2[p], v0, v1);
            s_diag[2 * p] = v0; s_diag[2 * p + 1] = v1;
        }
    }
    mlp(row, col, dist, out2);

    const int warp = tid >> 5, ln = tid & 31;
    const int rsel = r1 ? 0 : 16;

    // ---- segmented per-row/head max ----
    #pragma unroll
    for (int p = 0; p < 8; p++) {
        float v0, v1; upk2(out2[p], v0, v1);
        float a0 = r1 ? v0 : -INFINITY, a1 = r1 ? v1 : -INFINITY;
        float c0 = r1 ? -INFINITY : v0, c1 = r1 ? -INFINITY : v1;
        #pragma unroll
        for (int off = 16; off > 0; off >>= 1) {
            a0 = fmaxf(a0, __shfl_xor_sync(0xffffffffu, a0, off));
            a1 = fmaxf(a1, __shfl_xor_sync(0xffffffffu, a1, off));
            c0 = fmaxf(c0, __shfl_xor_sync(0xffffffffu, c0, off));
            c1 = fmaxf(c1, __shfl_xor_sync(0xffffffffu, c1, off));
        }
        if (ln == 0) {
            s_red[(2 * p) * 32 + warp]          = a0;
            s_red[(2 * p + 1) * 32 + warp]      = a1;
            s_red[(16 + 2 * p) * 32 + warp]     = c0;
            s_red[(16 + 2 * p + 1) * 32 + warp] = c1;
        }
    }
    __syncthreads();
    if (tid < 32) {
        float v = s_red[tid * 32];
        #pragma unroll
        for (int w = 1; w < 32; w++) v = fmaxf(v, s_red[tid * 32 + w]);
        if (tid >= 16) v = fmaxf(v, s_diag[tid - 16]);
        s_mx[tid] = v;
    }
    __syncthreads();
    if (tid < 16) s_dexp[tid] = __expf(s_diag[tid] - s_mx[16 + tid]);

    // ---- exp ----
    #pragma unroll
    for (int p = 0; p < 8; p++) {
        float v0, v1; upk2(out2[p], v0, v1);
        v0 = __expf(v0 - s_mx[rsel + 2 * p]);
        v1 = __expf(v1 - s_mx[rsel + 2 * p + 1]);
        out2[p] = pk2(v0, v1);
    }

    // ---- segmented per-row/head sum ----
    #pragma unroll
    for (int p = 0; p < 8; p++) {
        float v0, v1; upk2(out2[p], v0, v1);
        float a0 = r1 ? v0 : 0.f, a1 = r1 ? v1 : 0.f;
        float c0 = r1 ? 0.f : v0, c1 = r1 ? 0.f : v1;
        #pragma unroll
        for (int off = 16; off > 0; off >>= 1) {
            a0 += __shfl_xor_sync(0xffffffffu, a0, off);
            a1 += __shfl_xor_sync(0xffffffffu, a1, off);
            c0 += __shfl_xor_sync(0xffffffffu, c0, off);
            c1 += __shfl_xor_sync(0xffffffffu, c1, off);
        }
        if (ln == 0) {
            s_red[(2 * p) * 32 + warp]          = a0;
            s_red[(2 * p + 1) * 32 + warp]      = a1;
            s_red[(16 + 2 * p) * 32 + warp]     = c0;
            s_red[(16 + 2 * p + 1) * 32 + warp] = c1;
        }
    }
    __syncthreads();
    if (tid < 32) {
        float v = 0.0f;
        #pragma unroll
        for (int w = 0; w < 32; w++) v += s_red[tid * 32 + w];
        if (tid >= 16) v += s_dexp[tid - 16];
        s_inv[tid] = 1.0f / v;
    }
    __syncthreads();

    // ---- write main element ----
    {
        long long rb = bb + (long long)row * Lq;
        #pragma unroll
        for (int p = 0; p < 8; p++) {
            float v0, v1; upk2(out2[p], v0, v1);
            float w0 = v0 * s_inv[rsel + 2 * p];
            float w1v = v1 * s_inv[rsel + 2 * p + 1];
            bf16 h0 = __float2bfloat16(w0);
            bf16 h1 = __float2bfloat16(w1v);
            long long off0 = rb + (long long)(2 * p) * (Lq * Lq) + col;
            long long off1 = rb + (long long)(2 * p + 1) * (Lq * Lq) + col;
            whi[off0] = h0; wlo[off0] = __float2bfloat16(w0 - __bfloat162float(h0));
            whi[off1] = h1; wlo[off1] = __float2bfloat16(w1v - __bfloat162float(h1));
        }
    }
    // ---- write diagonal (i2, i2) ----
    if (tid < 16) {
        float wv = s_dexp[tid] * s_inv[16 + tid];
        bf16 hv = __float2bfloat16(wv);
        long long offd = bb + (long long)tid * (Lq * Lq) + (long long)i2 * Lq + i2;
        whi[offd] = hv;
        wlo[offd] = __float2bfloat16(wv - __bfloat162float(hv));
    }
    // ---- zero the upper triangles ----
    const bf16 z = __float2bfloat16(0.0f);
    if (tid > i1) {                       // row i1, j in (i1, 1023]
        long long zb = bb + (long long)i1 * Lq + tid;
        #pragma unroll
        for (int h = 0; h < 16; h++) {
            whi[zb + (long long)h * (Lq * Lq)] = z;
            wlo[zb + (long long)h * (Lq * Lq)] = z;
        }
    } else if (tid < i1) {                // row i2, j in (i2, 1023]
        long long zb = bb + (long long)i2 * Lq + (i2 + 1 + tid);
        #pragma unroll
        for (int h = 0; h < 16; h++) {
            whi[zb + (long long)h * (Lq * Lq)] = z;
            wlo[zb + (long long)h * (Lq * Lq)] = z;
        }
    }
}

// ---------------- launch ----------------------------------------------------
extern "C" void kernel_launch(void* const* d_in, const int* in_sizes, int n_in,
                              void* d_out, int out_size)
{
    const float* x     = (const float*)d_in[0];
    const float* w_qkv = (const float*)d_in[1];
    const float* w_o   = (const float*)d_in[2];
    const float* log_p = (const float*)d_in[3];
    const float* log_a = (const float*)d_in[4];
    const float* w1    = (const float*)d_in[5];
    const float* b1    = (const float*)d_in[6];
    const float* w2    = (const float*)d_in[7];
    const float* b2    = (const float*)d_in[8];
    float* out = (float*)d_out;
    (void)in_sizes; (void)n_in; (void)out_size;

    float *qkv, *sc, *kc, *ktab;
    bf16 *qhi, *qlo, *khi, *klo, *vThi, *vTlo, *whi, *wlo;
    bf16 *xhi, *xlo, *wqT_hi, *wqT_lo, *attnhi, *attnlo, *woT_hi, *woT_lo;
    cudaGetSymbolAddress((void**)&qkv,  g_qkv);
    cudaGetSymbolAddress((void**)&sc,   g_sc);
    cudaGetSymbolAddress((void**)&kc,   g_kc);
    cudaGetSymbolAddress((void**)&ktab, g_ktab);
    cudaGetSymbolAddress((void**)&qhi,  g_qhi);
    cudaGetSymbolAddress((void**)&qlo,  g_qlo);
    cudaGetSymbolAddress((void**)&khi,  g_khi);
    cudaGetSymbolAddress((void**)&klo,  g_klo);
    cudaGetSymbolAddress((void**)&vThi, g_vThi);
    cudaGetSymbolAddress((void**)&vTlo, g_vTlo);
    cudaGetSymbolAddress((void**)&whi,  g_whi);
    cudaGetSymbolAddress((void**)&wlo,  g_wlo);
    cudaGetSymbolAddress((void**)&xhi,    g_xhi);
    cudaGetSymbolAddress((void**)&xlo,    g_xlo);
    cudaGetSymbolAddress((void**)&wqT_hi, g_wqkvT_hi);
    cudaGetSymbolAddress((void**)&wqT_lo, g_wqkvT_lo);
    cudaGetSymbolAddress((void**)&attnhi, g_attnhi);
    cudaGetSymbolAddress((void**)&attnlo, g_attnlo);
    cudaGetSymbolAddress((void**)&woT_hi, g_woT_hi);
    cudaGetSymbolAddress((void**)&woT_lo, g_woT_lo);

    static int smem_set = 0;
    if (!smem_set) {
        cudaFuncSetAttribute(hgemm_kernel<128, 0, 0, 0>,
                             cudaFuncAttributeMaxDynamicSharedMemorySize, 3 * 32768);
        cudaFuncSetAttribute(hgemm_kernel<128, 1, 0, 0>,
                             cudaFuncAttributeMaxDynamicSharedMemorySize, 3 * 32768);
        cudaFuncSetAttribute(hgemm_kernel<64, 0, 1, 1>,
                             cudaFuncAttributeMaxDynamicSharedMemorySize, 3 * 24576);
        smem_set = 1;
    }

    const int M = Bq * Lq;           // 2048
    const int TH = 3 * Hq * Dq;      // 3072

    // 0) DAPE tables
    dape_pre_kernel<<<1024, 32>>>(w1, b1, log_p, log_a, kc, ktab);

    // 1) conversions for qkv GEMM
    conv_split_kernel<<<(M * HIDq) / 256, 256>>>(x, xhi, xlo, M * HIDq);
    conv_split_trans_kernel<<<dim3(TH / 32, HIDq / 32), dim3(32, 8)>>>(
        w_qkv, wqT_hi, wqT_lo, HIDq, TH);

    // 2) qkv = x @ w_qkv (tensor cores)
    hgemm_kernel<128, 0, 0, 0><<<dim3(TH / 128, M / 128), 256, 3 * 32768>>>(
        xhi, xlo, wqT_hi, wqT_lo, qkv, nullptr, nullptr,
        M, TH, HIDq, HIDq, HIDq, TH, 0, 0, 0, 1.0f);

    // 3) split + RoPE -> bf16 hi/lo q,k + transposed v
    rope_split_kernel<<<Bq * Hq * (Lq / 32), 256>>>(qkv, qhi, qlo, khi, klo, vThi, vTlo);

    // 4) scores = (q @ k^T)/8, batched 32, causal tile skip (tensor cores)
    hgemm_kernel<128, 1, 0, 0><<<dim3(Lq / 128, Lq / 128, Bq * Hq), 256, 3 * 32768>>>(
        qhi, qlo, khi, klo, sc, nullptr, nullptr,
        Lq, Lq, Dq, Dq, Dq, Lq,
        (long long)Lq * Dq, (long long)Lq * Dq, (long long)Lq * Lq, 0.125f);

    // 5) fused kerple + DAPE MLP + causal softmax (wedge-paired) -> bf16 weights
    dape_softmax_kernel<<<Bq * 512, 1024>>>(sc, whi, wlo, w1, w2, b2, kc, ktab);

    // 6) attn = weights @ v (tensor cores, causal-K, bf16 hi/lo out in (B,L,H*D))
    hgemm_kernel<64, 0, 1, 1><<<dim3(1, Lq / 128, Bq * Hq), 256, 3 * 24576>>>(
        whi, wlo, vThi, vTlo, nullptr, attnhi, attnlo,
        Lq, Dq, Lq, Lq, Lq, HIDq,
        (long long)Lq * Lq, (long long)Dq * Lq, 0, 1.0f);

    // 7) out = attn @ w_o (tensor cores)
    conv_split_trans_kernel<<<dim3(HIDq / 32, HIDq / 32), dim3(32, 8)>>>(
        w_o, woT_hi, woT_lo, HIDq, HIDq);
    hgemm_kernel<128, 0, 0, 0><<<dim3(HIDq / 128, M / 128), 256, 3 * 32768>>>(
        attnhi, attnlo, woT_hi, woT_lo, out, nullptr, nullptr,
        M, HIDq, HIDq, HIDq, HIDq, HIDq, 0, 0, 0, 1.0f);
}

// round 10
// speedup vs baseline: 1.0369x; 1.0369x over previous
#include <cuda_runtime.h>
#include <cuda_bf16.h>
#include <math.h>

#define Bq   2
#define Lq   1024
#define Hq   16
#define Dq   64
#define HIDq 1024

typedef __nv_bfloat16 bf16;
typedef unsigned long long ull;

// ---------------- scratch (static device globals; no runtime alloc) ----------
__device__ float g_qkv[Bq * Lq * 3 * Hq * Dq];                  // (B,L,3,H,D)
__device__ float g_sc[(long long)Bq * Hq * Lq * Lq];            // (B,H,L,L) fp32 scores

__device__ bf16 g_qhi[Bq * Hq * Lq * Dq], g_qlo[Bq * Hq * Lq * Dq];   // (B,H,L,D)
__device__ bf16 g_khi[Bq * Hq * Lq * Dq], g_klo[Bq * Hq * Lq * Dq];
__device__ bf16 g_vThi[Bq * Hq * Dq * Lq], g_vTlo[Bq * Hq * Dq * Lq]; // (B,H,D,L)
__device__ bf16 g_whi[(long long)Bq * Hq * Lq * Lq];                  // weights hi
__device__ bf16 g_wlo[(long long)Bq * Hq * Lq * Lq];                  // weights lo

__device__ bf16 g_xhi[2048 * 1024], g_xlo[2048 * 1024];
__device__ bf16 g_wqkvT_hi[3072 * 1024], g_wqkvT_lo[3072 * 1024];
__device__ bf16 g_attnhi[2048 * 1024], g_attnlo[2048 * 1024];   // (B,L,H*D)
__device__ bf16 g_woT_hi[1024 * 1024], g_woT_lo[1024 * 1024];

// DAPE precomputed tables
__device__ float g_kc[32 * 1024];     // [o][dist]
__device__ float g_ktab[16 * 1024];   // [h][dist]

// ---------------- f32x2 packed helpers ---------------------------------------
__device__ __forceinline__ ull pk2(float lo, float hi) {
    ull r; asm("mov.b64 %0,{%1,%2};" : "=l"(r) : "f"(lo), "f"(hi)); return r;
}
__device__ __forceinline__ void upk2(ull v, float& lo, float& hi) {
    asm("mov.b64 {%0,%1},%2;" : "=f"(lo), "=f"(hi) : "l"(v));
}
__device__ __forceinline__ ull ffma2(ull a, ull b, ull c) {
    ull d; asm("fma.rn.f32x2 %0,%1,%2,%3;" : "=l"(d) : "l"(a), "l"(b), "l"(c));
    return d;
}

// ======================= split-bf16 tensor-core GEMM ========================
#define BM 128
#define BK 32
#define NSTG 3

__device__ __forceinline__ void ldm_x4(unsigned r[4], unsigned addr) {
    asm volatile("ldmatrix.sync.aligned.m8n8.x4.shared.b16 {%0,%1,%2,%3}, [%4];"
        : "=r"(r[0]), "=r"(r[1]), "=r"(r[2]), "=r"(r[3]) : "r"(addr));
}
__device__ __forceinline__ void mma16816(float c[4], const unsigned a[4],
                                         unsigned b0, unsigned b1) {
    asm volatile("mma.sync.aligned.m16n8k16.row.col.f32.bf16.bf16.f32 "
        "{%0,%1,%2,%3},{%4,%5,%6,%7},{%8,%9},{%0,%1,%2,%3};"
        : "+f"(c[0]), "+f"(c[1]), "+f"(c[2]), "+f"(c[3])
        : "r"(a[0]), "r"(a[1]), "r"(a[2]), "r"(a[3]), "r"(b0), "r"(b1));
}
__device__ __forceinline__ void cp16(unsigned saddr, const void* g) {
    asm volatile("cp.async.cg.shared.global [%0], [%1], 16;\n" :: "r"(saddr), "l"(g));
}

// C = alpha * A(M,K) x B(N,K)^T, split precision hh+hl+lh.
template <int BN_, int CJ, int CK, int OUT>
__global__ __launch_bounds__(256)
void hgemm_kernel(const bf16* __restrict__ Ahi, const bf16* __restrict__ Alo,
                  const bf16* __restrict__ Bhi, const bf16* __restrict__ Blo,
                  float* __restrict__ Cf, bf16* __restrict__ Chi, bf16* __restrict__ Clo,
                  int M, int N, int K, int lda, int ldb, int ldc,
                  long long sA, long long sB, long long sC, float alpha)
{
    constexpr int WCOL = BN_ / 4;
    constexpr int NT = WCOL / 16;
    constexpr unsigned BOFF = 16384u;
    constexpr unsigned BLO  = 16384u + BN_ * 64u;
    constexpr unsigned STG  = 16384u + BN_ * 128u;

    const int bz = blockIdx.z;
    Ahi += (long long)bz * sA;  Alo += (long long)bz * sA;
    Bhi += (long long)bz * sB;  Blo += (long long)bz * sB;

    const int bi = blockIdx.y * BM, bj = blockIdx.x * BN_;
    if (CJ && bj > bi + BM - 1) return;

    extern __shared__ bf16 smem[];
    const unsigned sgen = (unsigned)__cvta_generic_to_shared(smem);
    const int tid = threadIdx.x;
    const int wid = tid >> 5, lane = tid & 31;
    const int wm = wid >> 2, wn = wid & 3;

    float acc[4][2 * NT][4];
    #pragma unroll
    for (int a = 0; a < 4; a++)
        #pragma unroll
        for (int b = 0; b < 2 * NT; b++)
            #pragma unroll
            for (int c = 0; c < 4; c++) acc[a][b][c] = 0.f;

    const int kmax = CK ? (bi + BM < K ? bi + BM : K) : K;
    const int nkt = kmax / BK;

    auto load_stage = [&](int stage, int kt) {
        int k0 = kt * BK;
        unsigned sb = sgen + stage * STG;
        #pragma unroll
        for (int rep = 0; rep < 2; rep++) {
            int c = tid + rep * 256;
            int row = c >> 2, kc = c & 3;
            unsigned swc = (unsigned)(kc ^ ((row >> 1) & 3));
            unsigned so = sb + (unsigned)row * 64u + swc * 16u;
            cp16(so,         Ahi + (size_t)(bi + row) * lda + k0 + kc * 8);
            cp16(so + 8192u, Alo + (size_t)(bi + row) * lda + k0 + kc * 8);
        }
        #pragma unroll
        for (int rep = 0; rep < BN_ / 64; rep++) {
            int c = tid + rep * 256;
            int row = c >> 2, kc = c & 3;
            unsigned swc = (unsigned)(kc ^ ((row >> 1) & 3));
            unsigned so = sb + (unsigned)row * 64u + swc * 16u;
            cp16(so + BOFF, Bhi + (size_t)(bj + row) * ldb + k0 + kc * 8);
            cp16(so + BLO,  Blo + (size_t)(bj + row) * ldb + k0 + kc * 8);
        }
    };

    auto compute_stage = [&](int stage) {
        unsigned sb = sgen + stage * STG;
        #pragma unroll
        for (int ks = 0; ks < 2; ks++) {
            int r = lane & 15;
            int cc = ks * 2 + (lane >> 4);
            unsigned a_hi[4][4], a_lo[4][4];
            #pragma unroll
            for (int mt = 0; mt < 4; mt++) {
                int row = wm * 64 + mt * 16 + r;
                unsigned swc = (unsigned)(cc ^ ((row >> 1) & 3));
                unsigned addr = sb + (unsigned)row * 64u + swc * 16u;
                ldm_x4(a_hi[mt], addr);
                ldm_x4(a_lo[mt], addr + 8192u);
            }
            unsigned b_hi[NT][4], b_lo[NT][4];
            #pragma unroll
            for (int bt = 0; bt < NT; bt++) {
                int row = wn * WCOL + bt * 16 + r;
                unsigned swc = (unsigned)(cc ^ ((row >> 1) & 3));
                unsigned addr = sb + BOFF + (unsigned)row * 64u + swc * 16u;
                ldm_x4(b_hi[bt], addr);
                ldm_x4(b_lo[bt], addr + (BN_ * 64u));
            }
            // ---- three passes: no back-to-back dependent MMAs on one acc ----
            #pragma unroll
            for (int mt = 0; mt < 4; mt++)
                #pragma unroll
                for (int n = 0; n < 2 * NT; n++) {
                    int bt = n >> 1, sel = n & 1;
                    mma16816(acc[mt][n], a_hi[mt], b_hi[bt][sel], b_hi[bt][sel + 2]);
                }
            #pragma unroll
            for (int mt = 0; mt < 4; mt++)
                #pragma unroll
                for (int n = 0; n < 2 * NT; n++) {
                    int bt = n >> 1, sel = n & 1;
                    mma16816(acc[mt][n], a_hi[mt], b_lo[bt][sel], b_lo[bt][sel + 2]);
                }
            #pragma unroll
            for (int mt = 0; mt < 4; mt++)
                #pragma unroll
                for (int n = 0; n < 2 * NT; n++) {
                    int bt = n >> 1, sel = n & 1;
                    mma16816(acc[mt][n], a_lo[mt], b_hi[bt][sel], b_hi[bt][sel + 2]);
                }
        }
    };

    #pragma unroll
    for (int s = 0; s < NSTG - 1; s++) {
        if (s < nkt) load_stage(s, s);
        asm volatile("cp.async.commit_group;\n");
    }
    for (int kt = 0; kt < nkt; kt++) {
        asm volatile("cp.async.wait_group %0;\n" :: "n"(NSTG - 2));
        __syncthreads();
        int kn = kt + NSTG - 1;
        if (kn < nkt) load_stage(kn % NSTG, kn);
        asm volatile("cp.async.commit_group;\n");
        compute_stage(kt % NSTG);
    }

    #pragma unroll
    for (int mt = 0; mt < 4; mt++) {
        int r0 = bi + wm * 64 + mt * 16 + (lane >> 2);
        #pragma unroll
        for (int n = 0; n < 2 * NT; n++) {
            int col = bj + wn * WCOL + (n >> 1) * 16 + (n & 1) * 8 + 2 * (lane & 3);
            if (OUT == 0) {
                float* C = Cf + (long long)bz * sC;
                float2 v0 = {alpha * acc[mt][n][0], alpha * acc[mt][n][1]};
                float2 v1 = {alpha * acc[mt][n][2], alpha * acc[mt][n][3]};
                *(float2*)&C[(size_t)r0 * ldc + col] = v0;
                *(float2*)&C[(size_t)(r0 + 8) * ldc + col] = v1;
            } else {
                long long base = (long long)(bz >> 4) * ((long long)Lq * HIDq)
                               + (long long)(bz & 15) * Dq;
                #pragma unroll
                for (int rr = 0; rr < 2; rr++) {
                    float va = acc[mt][n][rr * 2], vb = acc[mt][n][rr * 2 + 1];
                    bf16 ha = __float2bfloat16(va), hb = __float2bfloat16(vb);
                    bf16 la = __float2bfloat16(va - __bfloat162float(ha));
                    bf16 lb = __float2bfloat16(vb - __bfloat162float(hb));
                    size_t off = base + (size_t)(r0 + rr * 8) * ldc + col;
                    *(__nv_bfloat162*)&Chi[off] = __nv_bfloat162(ha, hb);
                    *(__nv_bfloat162*)&Clo[off] = __nv_bfloat162(la, lb);
                }
            }
        }
    }
}

// ---------------- fp32 -> bf16 hi/lo conversion kernels ----------------------
__global__ void conv_split_kernel(const float* __restrict__ src,
                                  bf16* __restrict__ hi, bf16* __restrict__ lo, int n)
{
    int i = blockIdx.x * blockDim.x + threadIdx.x;
    if (i >= n) return;
    float v = src[i];
    bf16 h = __float2bfloat16(v);
    hi[i] = h;
    lo[i] = __float2bfloat16(v - __bfloat162float(h));
}

__global__ void conv_split_trans_kernel(const float* __restrict__ W,
                                        bf16* __restrict__ hi, bf16* __restrict__ lo,
                                        int K, int N)
{
    __shared__ float t[32][33];
    int k0 = blockIdx.y * 32, n0 = blockIdx.x * 32;
    int tx = threadIdx.x, ty = threadIdx.y;
    #pragma unroll
    for (int r = ty; r < 32; r += 8)
        t[r][tx] = W[(size_t)(k0 + r) * N + n0 + tx];
    __syncthreads();
    #pragma unroll
    for (int r = ty; r < 32; r += 8) {
        float v = t[tx][r];
        bf16 h = __float2bfloat16(v);
        hi[(size_t)(n0 + r) * K + k0 + tx] = h;
        lo[(size_t)(n0 + r) * K + k0 + tx] = __float2bfloat16(v - __bfloat162float(h));
    }
}

// ---------------- qkv split + RoPE -> bf16 hi/lo (q,k) + transposed v -------
__global__ __launch_bounds__(256)
void rope_split_kernel(const float* __restrict__ qkv,
                       bf16* __restrict__ qhi, bf16* __restrict__ qlo,
                       bf16* __restrict__ khi, bf16* __restrict__ klo,
                       bf16* __restrict__ vThi, bf16* __restrict__ vTlo)
{
    __shared__ float sv[32][65];
    int bid = blockIdx.x;
    int l0 = (bid & 31) * 32;
    int h = (bid >> 5) & 15;
    int b = bid >> 9;
    int tid = threadIdx.x;

    #pragma unroll
    for (int e = 0; e < 8; e++) {
        int idx = tid + e * 256;
        int d = idx & 63, lr = idx >> 6;
        int l = l0 + lr;
        long long base = ((long long)(b * Lq + l) * 3) * (Hq * Dq) + h * Dq;
        float qa = qkv[base + d];
        float ka = qkv[base + Hq * Dq + d];
        float vv = qkv[base + 2 * Hq * Dq + d];
        int dp = (d < 32) ? d + 32 : d - 32;
        float qb = qkv[base + dp];
        float kb = qkv[base + Hq * Dq + dp];

        int fi = (d < 32) ? d : d - 32;
        float ang = (float)l * powf(10000.0f, -(float)fi / 32.0f);
        float c = cosf(ang), s = sinf(ang);
        float sgn = (d < 32) ? -1.0f : 1.0f;

        float qv = qa * c + sgn * qb * s;
        float kv = ka * c + sgn * kb * s;

        long long o = ((long long)(b * Hq + h) * Lq + l) * Dq + d;
        bf16 qh = __float2bfloat16(qv), kh = __float2bfloat16(kv);
        qhi[o] = qh; qlo[o] = __float2bfloat16(qv - __bfloat162float(qh));
        khi[o] = kh; klo[o] = __float2bfloat16(kv - __bfloat162float(kh));
        sv[lr][d] = vv;
    }
    __syncthreads();
    #pragma unroll
    for (int e = 0; e < 8; e++) {
        int idx = tid + e * 256;
        int lr = idx & 31, d = idx >> 5;
        float vv = sv[lr][d];
        bf16 vh = __float2bfloat16(vv);
        long long o = ((long long)(b * Hq + h) * Dq + d) * Lq + l0 + lr;
        vThi[o] = vh;
        vTlo[o] = __float2bfloat16(vv - __bfloat162float(vh));
    }
}

// ---------------- DAPE tables: kc[o][dist], ktab[h][dist] --------------------
__global__ void dape_pre_kernel(const float* __restrict__ w1, const float* __restrict__ b1,
                                const float* __restrict__ log_p, const float* __restrict__ log_a,
                                float* __restrict__ kc_t, float* __restrict__ ktab_t)
{
    int dist = blockIdx.x;
    int t = threadIdx.x;    // 32
    __shared__ float kv[16];
    if (t < 16) {
        float p = log1pf(expf(log_p[t]));
        float a = log1pf(expf(log_a[t]));
        float kvv = -p * log1pf(a * (float)dist);
        kv[t] = kvv;
        ktab_t[t * 1024 + dist] = kvv;
    }
    __syncthreads();
    float acc = b1[t];
    #pragma unroll
    for (int h = 0; h < 16; h++) acc += kv[h] * w1[(16 + h) * 32 + t];
    kc_t[t * 1024 + dist] = acc;
}

// ---------------- fused DAPE MLP + kerple + causal softmax (f32x2) ----------
__global__ __launch_bounds__(1024, 1)
void dape_softmax_kernel(const float* __restrict__ scores,
                         bf16* __restrict__ whi, bf16* __restrict__ wlo,
                         const float* __restrict__ w1, const float* __restrict__ w2,
                         const float* __restrict__ b2,
                         const float* __restrict__ kc_t, const float* __restrict__ ktab_t)
{
    __shared__ ull s_w1p[32 * 8];
    __shared__ ull s_w2p[32 * 8];
    __shared__ float s_b2[16];
    __shared__ float s_red[16 * 32];
    __shared__ float s_bc[16];

    int tid = threadIdx.x;
    int i = blockIdx.x & (Lq - 1);
    int b = blockIdx.x >> 10;

    if (tid < 256) {
        int o = tid >> 3, p = tid & 7;
        s_w1p[o * 8 + p] = pk2(w1[(2 * p) * 32 + o], w1[(2 * p + 1) * 32 + o]);
        s_w2p[o * 8 + p] = pk2(w2[o * 16 + 2 * p], w2[o * 16 + 2 * p + 1]);
    }
    if (tid < 16) s_b2[tid] = b2[tid];
    __syncthreads();

    long long base0 = (long long)b * (Hq * Lq * Lq) + (long long)i * Lq;
    int j = tid;
    ull out2[8];

    if (j <= i) {
        int dist = i - j;
        ull s2[8];
        #pragma unroll
        for (int p = 0; p < 8; p++) {
            float s0 = scores[base0 + (long long)(2 * p)     * (Lq * Lq) + j];
            float s1 = scores[base0 + (long long)(2 * p + 1) * (Lq * Lq) + j];
            s2[p] = pk2(s0, s1);
            float k0 = ktab_t[(2 * p) * 1024 + dist];
            float k1 = ktab_t[(2 * p + 1) * 1024 + dist];
            out2[p] = pk2(s0 + k0 + s_b2[2 * p], s1 + k1 + s_b2[2 * p + 1]);
        }
        #pragma unroll 4
        for (int o = 0; o < 32; o++) {
            ull acc2 = pk2(kc_t[o * 1024 + dist], 0.0f);
            #pragma unroll
            for (int p = 0; p < 8; p++) acc2 = ffma2(s2[p], s_w1p[o * 8 + p], acc2);
            float a0, a1; upk2(acc2, a0, a1);
            float acc = a0 + a1;
            float u = 0.7978845608f * (acc + 0.044715f * acc * acc * acc);
            float th; asm("tanh.approx.f32 %0,%1;" : "=f"(th) : "f"(u));
            float g = 0.5f * acc * (1.0f + th);
            ull g2 = pk2(g, g);
            #pragma unroll
            for (int p = 0; p < 8; p++) out2[p] = ffma2(g2, s_w2p[o * 8 + p], out2[p]);
        }
    } else {
        #pragma unroll
        for (int p = 0; p < 8; p++) out2[p] = pk2(-INFINITY, -INFINITY);
    }

    int warp = tid >> 5, ln = tid & 31;

    #pragma unroll
    for (int p = 0; p < 8; p++) {
        float v0, v1; upk2(out2[p], v0, v1);
        #pragma unroll
        for (int off = 16; off > 0; off >>= 1) {
            v0 = fmaxf(v0, __shfl_xor_sync(0xffffffffu, v0, off));
            v1 = fmaxf(v1, __shfl_xor_sync(0xffffffffu, v1, off));
        }
        if (ln == 0) { s_red[(2 * p) * 32 + warp] = v0; s_red[(2 * p + 1) * 32 + warp] = v1; }
    }
    __syncthreads();
    if (tid < 16) {
        float v = s_red[tid * 32];
        #pragma unroll
        for (int w = 1; w < 32; w++) v = fmaxf(v, s_red[tid * 32 + w]);
        s_bc[tid] = v;
    }
    __syncthreads();

    #pragma unroll
    for (int p = 0; p < 8; p++) {
        float v0, v1; upk2(out2[p], v0, v1);
        v0 = __expf(v0 - s_bc[2 * p]);
        v1 = __expf(v1 - s_bc[2 * p + 1]);
        out2[p] = pk2(v0, v1);
    }
    __syncthreads();
    #pragma unroll
    for (int p = 0; p < 8; p++) {
        float v0, v1; upk2(out2[p], v0, v1);
        #pragma unroll
        for (int off = 16; off > 0; off >>= 1) {
            v0 += __shfl_xor_sync(0xffffffffu, v0, off);
            v1 += __shfl_xor_sync(0xffffffffu, v1, off);
        }
        if (ln == 0) { s_red[(2 * p) * 32 + warp] = v0; s_red[(2 * p + 1) * 32 + warp] = v1; }
    }
    __syncthreads();
    if (tid < 16) {
        float v = 0.0f;
        #pragma unroll
        for (int w = 0; w < 32; w++) v += s_red[tid * 32 + w];
        s_bc[tid] = 1.0f / v;
    }
    __syncthreads();

    #pragma unroll
    for (int p = 0; p < 8; p++) {
        float v0, v1; upk2(out2[p], v0, v1);
        float w0 = v0 * s_bc[2 * p];
        float w1v = v1 * s_bc[2 * p + 1];
        bf16 h0 = __float2bfloat16(w0);
        bf16 h1 = __float2bfloat16(w1v);
        long long off0 = base0 + (long long)(2 * p) * (Lq * Lq) + j;
        long long off1 = base0 + (long long)(2 * p + 1) * (Lq * Lq) + j;
        whi[off0] = h0; wlo[off0] = __float2bfloat16(w0 - __bfloat162float(h0));
        whi[off1] = h1; wlo[off1] = __float2bfloat16(w1v - __bfloat162float(h1));
    }
}

// ---------------- launch ----------------------------------------------------
extern "C" void kernel_launch(void* const* d_in, const int* in_sizes, int n_in,
                              void* d_out, int out_size)
{
    const float* x     = (const float*)d_in[0];
    const float* w_qkv = (const float*)d_in[1];
    const float* w_o   = (const float*)d_in[2];
    const float* log_p = (const float*)d_in[3];
    const float* log_a = (const float*)d_in[4];
    const float* w1    = (const float*)d_in[5];
    const float* b1    = (const float*)d_in[6];
    const float* w2    = (const float*)d_in[7];
    const float* b2    = (const float*)d_in[8];
    float* out = (float*)d_out;
    (void)in_sizes; (void)n_in; (void)out_size;

    float *qkv, *sc, *kc, *ktab;
    bf16 *qhi, *qlo, *khi, *klo, *vThi, *vTlo, *whi, *wlo;
    bf16 *xhi, *xlo, *wqT_hi, *wqT_lo, *attnhi, *attnlo, *woT_hi, *woT_lo;
    cudaGetSymbolAddress((void**)&qkv,  g_qkv);
    cudaGetSymbolAddress((void**)&sc,   g_sc);
    cudaGetSymbolAddress((void**)&kc,   g_kc);
    cudaGetSymbolAddress((void**)&ktab, g_ktab);
    cudaGetSymbolAddress((void**)&qhi,  g_qhi);
    cudaGetSymbolAddress((void**)&qlo,  g_qlo);
    cudaGetSymbolAddress((void**)&khi,  g_khi);
    cudaGetSymbolAddress((void**)&klo,  g_klo);
    cudaGetSymbolAddress((void**)&vThi, g_vThi);
    cudaGetSymbolAddress((void**)&vTlo, g_vTlo);
    cudaGetSymbolAddress((void**)&whi,  g_whi);
    cudaGetSymbolAddress((void**)&wlo,  g_wlo);
    cudaGetSymbolAddress((void**)&xhi,    g_xhi);
    cudaGetSymbolAddress((void**)&xlo,    g_xlo);
    cudaGetSymbolAddress((void**)&wqT_hi, g_wqkvT_hi);
    cudaGetSymbolAddress((void**)&wqT_lo, g_wqkvT_lo);
    cudaGetSymbolAddress((void**)&attnhi, g_attnhi);
    cudaGetSymbolAddress((void**)&attnlo, g_attnlo);
    cudaGetSymbolAddress((void**)&woT_hi, g_woT_hi);
    cudaGetSymbolAddress((void**)&woT_lo, g_woT_lo);

    static int smem_set = 0;
    if (!smem_set) {
        cudaFuncSetAttribute(hgemm_kernel<128, 0, 0, 0>,
                             cudaFuncAttributeMaxDynamicSharedMemorySize, 3 * 32768);
        cudaFuncSetAttribute(hgemm_kernel<128, 1, 0, 0>,
                             cudaFuncAttributeMaxDynamicSharedMemorySize, 3 * 32768);
        cudaFuncSetAttribute(hgemm_kernel<64, 0, 1, 1>,
                             cudaFuncAttributeMaxDynamicSharedMemorySize, 3 * 24576);
        smem_set = 1;
    }

    const int M = Bq * Lq;           // 2048
    const int TH = 3 * Hq * Dq;      // 3072

    // 0) DAPE tables
    dape_pre_kernel<<<1024, 32>>>(w1, b1, log_p, log_a, kc, ktab);

    // 1) conversions for qkv GEMM
    conv_split_kernel<<<(M * HIDq) / 256, 256>>>(x, xhi, xlo, M * HIDq);
    conv_split_trans_kernel<<<dim3(TH / 32, HIDq / 32), dim3(32, 8)>>>(
        w_qkv, wqT_hi, wqT_lo, HIDq, TH);

    // 2) qkv = x @ w_qkv (tensor cores)
    hgemm_kernel<128, 0, 0, 0><<<dim3(TH / 128, M / 128), 256, 3 * 32768>>>(
        xhi, xlo, wqT_hi, wqT_lo, qkv, nullptr, nullptr,
        M, TH, HIDq, HIDq, HIDq, TH, 0, 0, 0, 1.0f);

    // 3) split + RoPE -> bf16 hi/lo q,k + transposed v
    rope_split_kernel<<<Bq * Hq * (Lq / 32), 256>>>(qkv, qhi, qlo, khi, klo, vThi, vTlo);

    // 4) scores = (q @ k^T)/8, batched 32, causal tile skip (tensor cores)
    hgemm_kernel<128, 1, 0, 0><<<dim3(Lq / 128, Lq / 128, Bq * Hq), 256, 3 * 32768>>>(
        qhi, qlo, khi, klo, sc, nullptr, nullptr,
        Lq, Lq, Dq, Dq, Dq, Lq,
        (long long)Lq * Dq, (long long)Lq * Dq, (long long)Lq * Lq, 0.125f);

    // 5) fused kerple + DAPE MLP + causal softmax -> bf16 hi/lo weights
    dape_softmax_kernel<<<Bq * Lq, 1024>>>(sc, whi, wlo, w1, w2, b2, kc, ktab);

    // 6) attn = weights @ v (tensor cores, causal-K, bf16 hi/lo out in (B,L,H*D))
    hgemm_kernel<64, 0, 1, 1><<<dim3(1, Lq / 128, Bq * Hq), 256, 3 * 24576>>>(
        whi, wlo, vThi, vTlo, nullptr, attnhi, attnlo,
        Lq, Dq, Lq, Lq, Lq, HIDq,
        (long long)Lq * Lq, (long long)Dq * Lq, 0, 1.0f);

    // 7) out = attn @ w_o (tensor cores)
    conv_split_trans_kernel<<<dim3(HIDq / 32, HIDq / 32), dim3(32, 8)>>>(
        w_o, woT_hi, woT_lo, HIDq, HIDq);
    hgemm_kernel<128, 0, 0, 0><<<dim3(HIDq / 128, M / 128), 256, 3 * 32768>>>(
        attnhi, attnlo, woT_hi, woT_lo, out, nullptr, nullptr,
        M, HIDq, HIDq, HIDq, HIDq, HIDq, 0, 0, 0, 1.0f);
}

// round 11
// speedup vs baseline: 1.1866x; 1.1444x over previous
#include <cuda_runtime.h>
#include <cuda_bf16.h>
#include <cuda_fp16.h>
#include <math.h>

#define Bq   2
#define Lq   1024
#define Hq   16
#define Dq   64
#define HIDq 1024

typedef __nv_bfloat16 bf16;
typedef unsigned long long ull;

// ---------------- scratch (static device globals; no runtime alloc) ----------
__device__ float g_qkv[Bq * Lq * 3 * Hq * Dq];                  // (B,L,3,H,D)
__device__ float g_sc[(long long)Bq * Hq * Lq * Lq];            // (B,H,L,L) fp32 scores

__device__ bf16 g_qhi[Bq * Hq * Lq * Dq], g_qlo[Bq * Hq * Lq * Dq];   // (B,H,L,D)
__device__ bf16 g_khi[Bq * Hq * Lq * Dq], g_klo[Bq * Hq * Lq * Dq];
__device__ bf16 g_vThi[Bq * Hq * Dq * Lq], g_vTlo[Bq * Hq * Dq * Lq]; // (B,H,D,L)
__device__ bf16 g_whi[(long long)Bq * Hq * Lq * Lq];                  // weights hi
__device__ bf16 g_wlo[(long long)Bq * Hq * Lq * Lq];                  // weights lo

// fp16 operand buffers (dense GEMMs: A single, B split)
__device__ __half g_xh[2048 * 1024];
__device__ __half g_wqkvTh_hi[3072 * 1024], g_wqkvTh_lo[3072 * 1024];
__device__ __half g_attnh[2048 * 1024];                               // (B,L,H*D)
__device__ __half g_woTh_hi[1024 * 1024], g_woTh_lo[1024 * 1024];

// DAPE precomputed tables
__device__ float g_kc[32 * 1024];     // [o][dist]
__device__ float g_ktab[16 * 1024];   // [h][dist]

// ---------------- f32x2 packed helpers ---------------------------------------
__device__ __forceinline__ ull pk2(float lo, float hi) {
    ull r; asm("mov.b64 %0,{%1,%2};" : "=l"(r) : "f"(lo), "f"(hi)); return r;
}
__device__ __forceinline__ void upk2(ull v, float& lo, float& hi) {
    asm("mov.b64 {%0,%1},%2;" : "=f"(lo), "=f"(hi) : "l"(v));
}
__device__ __forceinline__ ull ffma2(ull a, ull b, ull c) {
    ull d; asm("fma.rn.f32x2 %0,%1,%2,%3;" : "=l"(d) : "l"(a), "l"(b), "l"(c));
    return d;
}

// ======================= split tensor-core GEMM =============================
#define BM 128
#define BK 32
#define NSTG 3

__device__ __forceinline__ void ldm_x4(unsigned r[4], unsigned addr) {
    asm volatile("ldmatrix.sync.aligned.m8n8.x4.shared.b16 {%0,%1,%2,%3}, [%4];"
        : "=r"(r[0]), "=r"(r[1]), "=r"(r[2]), "=r"(r[3]) : "r"(addr));
}
template <int F16>
__device__ __forceinline__ void mma16816(float c[4], const unsigned a[4],
                                         unsigned b0, unsigned b1) {
    if (F16)
        asm volatile("mma.sync.aligned.m16n8k16.row.col.f32.f16.f16.f32 "
            "{%0,%1,%2,%3},{%4,%5,%6,%7},{%8,%9},{%0,%1,%2,%3};"
            : "+f"(c[0]), "+f"(c[1]), "+f"(c[2]), "+f"(c[3])
            : "r"(a[0]), "r"(a[1]), "r"(a[2]), "r"(a[3]), "r"(b0), "r"(b1));
    else
        asm volatile("mma.sync.aligned.m16n8k16.row.col.f32.bf16.bf16.f32 "
            "{%0,%1,%2,%3},{%4,%5,%6,%7},{%8,%9},{%0,%1,%2,%3};"
            : "+f"(c[0]), "+f"(c[1]), "+f"(c[2]), "+f"(c[3])
            : "r"(a[0]), "r"(a[1]), "r"(a[2]), "r"(a[3]), "r"(b0), "r"(b1));
}
__device__ __forceinline__ void cp16(unsigned saddr, const void* g) {
    asm volatile("cp.async.cg.shared.global [%0], [%1], 16;\n" :: "r"(saddr), "l"(g));
}

// C = alpha * A(M,K) x B(N,K)^T.
// F16: element type (1 = fp16, 0 = bf16) for the MMA.
// AS : A planes. AS=2 -> 3 passes (A·Bhi, A·Blo, Alo·Bhi). AS=1 -> 2 passes.
// CJ : causal output-tile skip. CK: clamp K at bi+BM. OUT: 0 fp32 C, 1 fp16 C.
template <int F16, int AS, int BN_, int CJ, int CK, int OUT>
__global__ __launch_bounds__(256)
void hgemm_kernel(const __half* __restrict__ Ahi, const __half* __restrict__ Alo,
                  const __half* __restrict__ Bhi, const __half* __restrict__ Blo,
                  float* __restrict__ Cf, __half* __restrict__ Ch,
                  int M, int N, int K, int lda, int ldb, int ldc,
                  long long sA, long long sB, long long sC, float alpha)
{
    constexpr int WCOL = BN_ / 4;
    constexpr int NT = WCOL / 16;
    constexpr unsigned BOFF = (unsigned)AS * 8192u;
    constexpr unsigned BLOF = BOFF + BN_ * 64u;
    constexpr unsigned STG  = (unsigned)AS * 8192u + BN_ * 128u;

    const int bz = blockIdx.z;
    Ahi += (long long)bz * sA;
    if (AS == 2) Alo += (long long)bz * sA;
    Bhi += (long long)bz * sB;  Blo += (long long)bz * sB;

    const int bi = blockIdx.y * BM, bj = blockIdx.x * BN_;
    if (CJ && bj > bi + BM - 1) return;

    extern __shared__ __half smem[];
    const unsigned sgen = (unsigned)__cvta_generic_to_shared(smem);
    const int tid = threadIdx.x;
    const int wid = tid >> 5, lane = tid & 31;
    const int wm = wid >> 2, wn = wid & 3;

    float acc[4][2 * NT][4];
    #pragma unroll
    for (int a = 0; a < 4; a++)
        #pragma unroll
        for (int b = 0; b < 2 * NT; b++)
            #pragma unroll
            for (int c = 0; c < 4; c++) acc[a][b][c] = 0.f;

    const int kmax = CK ? (bi + BM < K ? bi + BM : K) : K;
    const int nkt = kmax / BK;

    auto load_stage = [&](int stage, int kt) {
        int k0 = kt * BK;
        unsigned sb = sgen + stage * STG;
        #pragma unroll
        for (int t = tid; t < 512; t += 256) {          // A: 128 rows x 4 chunks
            int row = t >> 2, kc = t & 3;
            unsigned swc = (unsigned)(kc ^ ((row >> 1) & 3));
            unsigned so = sb + (unsigned)row * 64u + swc * 16u;
            cp16(so, Ahi + (size_t)(bi + row) * lda + k0 + kc * 8);
            if (AS == 2)
                cp16(so + 8192u, Alo + (size_t)(bi + row) * lda + k0 + kc * 8);
        }
        #pragma unroll
        for (int t = tid; t < BN_ * 4; t += 256) {      // B: BN_ rows x 4 chunks
            int row = t >> 2, kc = t & 3;
            unsigned swc = (unsigned)(kc ^ ((row >> 1) & 3));
            unsigned so = sb + (unsigned)row * 64u + swc * 16u;
            cp16(so + BOFF, Bhi + (size_t)(bj + row) * ldb + k0 + kc * 8);
            cp16(so + BLOF, Blo + (size_t)(bj + row) * ldb + k0 + kc * 8);
        }
    };

    auto compute_stage = [&](int stage) {
        unsigned sb = sgen + stage * STG;
        #pragma unroll
        for (int ks = 0; ks < 2; ks++) {
            int r = lane & 15;
            int cc = ks * 2 + (lane >> 4);
            unsigned a_hi[4][4], a_lo[4][4];
            #pragma unroll
            for (int mt = 0; mt < 4; mt++) {
                int row = wm * 64 + mt * 16 + r;
                unsigned swc = (unsigned)(cc ^ ((row >> 1) & 3));
                unsigned addr = sb + (unsigned)row * 64u + swc * 16u;
                ldm_x4(a_hi[mt], addr);
                if (AS == 2) ldm_x4(a_lo[mt], addr + 8192u);
            }
            unsigned b_hi[NT][4], b_lo[NT][4];
            #pragma unroll
            for (int bt = 0; bt < NT; bt++) {
                int row = wn * WCOL + bt * 16 + r;
                unsigned swc = (unsigned)(cc ^ ((row >> 1) & 3));
                unsigned addr = sb + BOFF + (unsigned)row * 64u + swc * 16u;
                ldm_x4(b_hi[bt], addr);
                ldm_x4(b_lo[bt], addr + (BN_ * 64u));
            }
            #pragma unroll
            for (int mt = 0; mt < 4; mt++)
                #pragma unroll
                for (int n = 0; n < 2 * NT; n++) {
                    int bt = n >> 1, sel = n & 1;
                    mma16816<F16>(acc[mt][n], a_hi[mt], b_hi[bt][sel], b_hi[bt][sel + 2]);
                }
            #pragma unroll
            for (int mt = 0; mt < 4; mt++)
                #pragma unroll
                for (int n = 0; n < 2 * NT; n++) {
                    int bt = n >> 1, sel = n & 1;
                    mma16816<F16>(acc[mt][n], a_hi[mt], b_lo[bt][sel], b_lo[bt][sel + 2]);
                }
            if (AS == 2) {
                #pragma unroll
                for (int mt = 0; mt < 4; mt++)
                    #pragma unroll
                    for (int n = 0; n < 2 * NT; n++) {
                        int bt = n >> 1, sel = n & 1;
                        mma16816<F16>(acc[mt][n], a_lo[mt], b_hi[bt][sel], b_hi[bt][sel + 2]);
                    }
            }
        }
    };

    #pragma unroll
    for (int s = 0; s < NSTG - 1; s++) {
        if (s < nkt) load_stage(s, s);
        asm volatile("cp.async.commit_group;\n");
    }
    for (int kt = 0; kt < nkt; kt++) {
        asm volatile("cp.async.wait_group %0;\n" :: "n"(NSTG - 2));
        __syncthreads();
        int kn = kt + NSTG - 1;
        if (kn < nkt) load_stage(kn % NSTG, kn);
        asm volatile("cp.async.commit_group;\n");
        compute_stage(kt % NSTG);
    }

    #pragma unroll
    for (int mt = 0; mt < 4; mt++) {
        int r0 = bi + wm * 64 + mt * 16 + (lane >> 2);
        #pragma unroll
        for (int n = 0; n < 2 * NT; n++) {
            int col = bj + wn * WCOL + (n >> 1) * 16 + (n & 1) * 8 + 2 * (lane & 3);
            if (OUT == 0) {
                float* C = Cf + (long long)bz * sC;
                float2 v0 = {alpha * acc[mt][n][0], alpha * acc[mt][n][1]};
                float2 v1 = {alpha * acc[mt][n][2], alpha * acc[mt][n][3]};
                *(float2*)&C[(size_t)r0 * ldc + col] = v0;
                *(float2*)&C[(size_t)(r0 + 8) * ldc + col] = v1;
            } else {
                long long base = (long long)(bz >> 4) * ((long long)Lq * HIDq)
                               + (long long)(bz & 15) * Dq;
                #pragma unroll
                for (int rr = 0; rr < 2; rr++) {
                    __half2 hv = __floats2half2_rn(acc[mt][n][rr * 2],
                                                   acc[mt][n][rr * 2 + 1]);
                    size_t off = base + (size_t)(r0 + rr * 8) * ldc + col;
                    *(__half2*)&Ch[off] = hv;
                }
            }
        }
    }
}

// ---------------- conversion kernels -----------------------------------------
__global__ void conv_half_kernel(const float* __restrict__ src,
                                 __half* __restrict__ dst, int n)
{
    int i = blockIdx.x * blockDim.x + threadIdx.x;
    if (i < n) dst[i] = __float2half(src[i]);
}

// W (K,N) fp32 row-major -> fp16 hi/lo (N,K) row-major (transposed)
__global__ void conv_split_trans_h(const float* __restrict__ W,
                                   __half* __restrict__ hi, __half* __restrict__ lo,
                                   int K, int N)
{
    __shared__ float t[32][33];
    int k0 = blockIdx.y * 32, n0 = blockIdx.x * 32;
    int tx = threadIdx.x, ty = threadIdx.y;
    #pragma unroll
    for (int r = ty; r < 32; r += 8)
        t[r][tx] = W[(size_t)(k0 + r) * N + n0 + tx];
    __syncthreads();
    #pragma unroll
    for (int r = ty; r < 32; r += 8) {
        float v = t[tx][r];
        __half h = __float2half(v);
        hi[(size_t)(n0 + r) * K + k0 + tx] = h;
        lo[(size_t)(n0 + r) * K + k0 + tx] = __float2half(v - __half2float(h));
    }
}

// ---------------- qkv split + RoPE -> bf16 hi/lo (q,k) + transposed v -------
__global__ __launch_bounds__(256)
void rope_split_kernel(const float* __restrict__ qkv,
                       bf16* __restrict__ qhi, bf16* __restrict__ qlo,
                       bf16* __restrict__ khi, bf16* __restrict__ klo,
                       bf16* __restrict__ vThi, bf16* __restrict__ vTlo)
{
    __shared__ float sv[32][65];
    int bid = blockIdx.x;
    int l0 = (bid & 31) * 32;
    int h = (bid >> 5) & 15;
    int b = bid >> 9;
    int tid = threadIdx.x;

    #pragma unroll
    for (int e = 0; e < 8; e++) {
        int idx = tid + e * 256;
        int d = idx & 63, lr = idx >> 6;
        int l = l0 + lr;
        long long base = ((long long)(b * Lq + l) * 3) * (Hq * Dq) + h * Dq;
        float qa = qkv[base + d];
        float ka = qkv[base + Hq * Dq + d];
        float vv = qkv[base + 2 * Hq * Dq + d];
        int dp = (d < 32) ? d + 32 : d - 32;
        float qb = qkv[base + dp];
        float kb = qkv[base + Hq * Dq + dp];

        int fi = (d < 32) ? d : d - 32;
        float ang = (float)l * powf(10000.0f, -(float)fi / 32.0f);
        float c = cosf(ang), s = sinf(ang);
        float sgn = (d < 32) ? -1.0f : 1.0f;

        float qv = qa * c + sgn * qb * s;
        float kv = ka * c + sgn * kb * s;

        long long o = ((long long)(b * Hq + h) * Lq + l) * Dq + d;
        bf16 qh = __float2bfloat16(qv), kh = __float2bfloat16(kv);
        qhi[o] = qh; qlo[o] = __float2bfloat16(qv - __bfloat162float(qh));
        khi[o] = kh; klo[o] = __float2bfloat16(kv - __bfloat162float(kh));
        sv[lr][d] = vv;
    }
    __syncthreads();
    #pragma unroll
    for (int e = 0; e < 8; e++) {
        int idx = tid + e * 256;
        int lr = idx & 31, d = idx >> 5;
        float vv = sv[lr][d];
        bf16 vh = __float2bfloat16(vv);
        long long o = ((long long)(b * Hq + h) * Dq + d) * Lq + l0 + lr;
        vThi[o] = vh;
        vTlo[o] = __float2bfloat16(vv - __bfloat162float(vh));
    }
}

// ---------------- DAPE tables: kc[o][dist], ktab[h][dist] --------------------
__global__ void dape_pre_kernel(const float* __restrict__ w1, const float* __restrict__ b1,
                                const float* __restrict__ log_p, const float* __restrict__ log_a,
                                float* __restrict__ kc_t, float* __restrict__ ktab_t)
{
    int dist = blockIdx.x;
    int t = threadIdx.x;    // 32
    __shared__ float kv[16];
    if (t < 16) {
        float p = log1pf(expf(log_p[t]));
        float a = log1pf(expf(log_a[t]));
        float kvv = -p * log1pf(a * (float)dist);
        kv[t] = kvv;
        ktab_t[t * 1024 + dist] = kvv;
    }
    __syncthreads();
    float acc = b1[t];
    #pragma unroll
    for (int h = 0; h < 16; h++) acc += kv[h] * w1[(16 + h) * 32 + t];
    kc_t[t * 1024 + dist] = acc;
}

// ---------------- fused DAPE MLP + kerple + causal softmax (f32x2) ----------
__global__ __launch_bounds__(1024, 1)
void dape_softmax_kernel(const float* __restrict__ scores,
                         bf16* __restrict__ whi, bf16* __restrict__ wlo,
                         const float* __restrict__ w1, const float* __restrict__ w2,
                         const float* __restrict__ b2,
                         const float* __restrict__ kc_t, const float* __restrict__ ktab_t)
{
    __shared__ ull s_w1p[32 * 8];
    __shared__ ull s_w2p[32 * 8];
    __shared__ float s_b2[16];
    __shared__ float s_red[16 * 32];
    __shared__ float s_bc[16];

    int tid = threadIdx.x;
    int i = blockIdx.x & (Lq - 1);
    int b = blockIdx.x >> 10;

    if (tid < 256) {
        int o = tid >> 3, p = tid & 7;
        s_w1p[o * 8 + p] = pk2(w1[(2 * p) * 32 + o], w1[(2 * p + 1) * 32 + o]);
        s_w2p[o * 8 + p] = pk2(w2[o * 16 + 2 * p], w2[o * 16 + 2 * p + 1]);
    }
    if (tid < 16) s_b2[tid] = b2[tid];
    __syncthreads();

    long long base0 = (long long)b * (Hq * Lq * Lq) + (long long)i * Lq;
    int j = tid;
    ull out2[8];

    if (j <= i) {
        int dist = i - j;
        ull s2[8];
        #pragma unroll
        for (int p = 0; p < 8; p++) {
            float s0 = scores[base0 + (long long)(2 * p)     * (Lq * Lq) + j];
            float s1 = scores[base0 + (long long)(2 * p + 1) * (Lq * Lq) + j];
            s2[p] = pk2(s0, s1);
            float k0 = ktab_t[(2 * p) * 1024 + dist];
            float k1 = ktab_t[(2 * p + 1) * 1024 + dist];
            out2[p] = pk2(s0 + k0 + s_b2[2 * p], s1 + k1 + s_b2[2 * p + 1]);
        }
        #pragma unroll 4
        for (int o = 0; o < 32; o++) {
            ull acc2 = pk2(kc_t[o * 1024 + dist], 0.0f);
            #pragma unroll
            for (int p = 0; p < 8; p++) acc2 = ffma2(s2[p], s_w1p[o * 8 + p], acc2);
            float a0, a1; upk2(acc2, a0, a1);
            float acc = a0 + a1;
            float u = 0.7978845608f * (acc + 0.044715f * acc * acc * acc);
            float th; asm("tanh.approx.f32 %0,%1;" : "=f"(th) : "f"(u));
            float g = 0.5f * acc * (1.0f + th);
            ull g2 = pk2(g, g);
            #pragma unroll
            for (int p = 0; p < 8; p++) out2[p] = ffma2(g2, s_w2p[o * 8 + p], out2[p]);
        }
    } else {
        #pragma unroll
        for (int p = 0; p < 8; p++) out2[p] = pk2(-INFINITY, -INFINITY);
    }

    int warp = tid >> 5, ln = tid & 31;

    #pragma unroll
    for (int p = 0; p < 8; p++) {
        float v0, v1; upk2(out2[p], v0, v1);
        #pragma unroll
        for (int off = 16; off > 0; off >>= 1) {
            v0 = fmaxf(v0, __shfl_xor_sync(0xffffffffu, v0, off));
            v1 = fmaxf(v1, __shfl_xor_sync(0xffffffffu, v1, off));
        }
        if (ln == 0) { s_red[(2 * p) * 32 + warp] = v0; s_red[(2 * p + 1) * 32 + warp] = v1; }
    }
    __syncthreads();
    if (tid < 16) {
        float v = s_red[tid * 32];
        #pragma unroll
        for (int w = 1; w < 32; w++) v = fmaxf(v, s_red[tid * 32 + w]);
        s_bc[tid] = v;
    }
    __syncthreads();

    #pragma unroll
    for (int p = 0; p < 8; p++) {
        float v0, v1; upk2(out2[p], v0, v1);
        v0 = __expf(v0 - s_bc[2 * p]);
        v1 = __expf(v1 - s_bc[2 * p + 1]);
        out2[p] = pk2(v0, v1);
    }
    __syncthreads();
    #pragma unroll
    for (int p = 0; p < 8; p++) {
        float v0, v1; upk2(out2[p], v0, v1);
        #pragma unroll
        for (int off = 16; off > 0; off >>= 1) {
            v0 += __shfl_xor_sync(0xffffffffu, v0, off);
            v1 += __shfl_xor_sync(0xffffffffu, v1, off);
        }
        if (ln == 0) { s_red[(2 * p) * 32 + warp] = v0; s_red[(2 * p + 1) * 32 + warp] = v1; }
    }
    __syncthreads();
    if (tid < 16) {
        float v = 0.0f;
        #pragma unroll
        for (int w = 0; w < 32; w++) v += s_red[tid * 32 + w];
        s_bc[tid] = 1.0f / v;
    }
    __syncthreads();

    #pragma unroll
    for (int p = 0; p < 8; p++) {
        float v0, v1; upk2(out2[p], v0, v1);
        float w0 = v0 * s_bc[2 * p];
        float w1v = v1 * s_bc[2 * p + 1];
        bf16 h0 = __float2bfloat16(w0);
        bf16 h1 = __float2bfloat16(w1v);
        long long off0 = base0 + (long long)(2 * p) * (Lq * Lq) + j;
        long long off1 = base0 + (long long)(2 * p + 1) * (Lq * Lq) + j;
        whi[off0] = h0; wlo[off0] = __float2bfloat16(w0 - __bfloat162float(h0));
        whi[off1] = h1; wlo[off1] = __float2bfloat16(w1v - __bfloat162float(h1));
    }
}

// ---------------- launch ----------------------------------------------------
extern "C" void kernel_launch(void* const* d_in, const int* in_sizes, int n_in,
                              void* d_out, int out_size)
{
    const float* x     = (const float*)d_in[0];
    const float* w_qkv = (const float*)d_in[1];
    const float* w_o   = (const float*)d_in[2];
    const float* log_p = (const float*)d_in[3];
    const float* log_a = (const float*)d_in[4];
    const float* w1    = (const float*)d_in[5];
    const float* b1    = (const float*)d_in[6];
    const float* w2    = (const float*)d_in[7];
    const float* b2    = (const float*)d_in[8];
    float* out = (float*)d_out;
    (void)in_sizes; (void)n_in; (void)out_size;

    float *qkv, *sc, *kc, *ktab;
    bf16 *qhi, *qlo, *khi, *klo, *vThi, *vTlo, *whi, *wlo;
    __half *xh, *wqT_hi, *wqT_lo, *attnh, *woT_hi, *woT_lo;
    cudaGetSymbolAddress((void**)&qkv,  g_qkv);
    cudaGetSymbolAddress((void**)&sc,   g_sc);
    cudaGetSymbolAddress((void**)&kc,   g_kc);
    cudaGetSymbolAddress((void**)&ktab, g_ktab);
    cudaGetSymbolAddress((void**)&qhi,  g_qhi);
    cudaGetSymbolAddress((void**)&qlo,  g_qlo);
    cudaGetSymbolAddress((void**)&khi,  g_khi);
    cudaGetSymbolAddress((void**)&klo,  g_klo);
    cudaGetSymbolAddress((void**)&vThi, g_vThi);
    cudaGetSymbolAddress((void**)&vTlo, g_vTlo);
    cudaGetSymbolAddress((void**)&whi,  g_whi);
    cudaGetSymbolAddress((void**)&wlo,  g_wlo);
    cudaGetSymbolAddress((void**)&xh,     g_xh);
    cudaGetSymbolAddress((void**)&wqT_hi, g_wqkvTh_hi);
    cudaGetSymbolAddress((void**)&wqT_lo, g_wqkvTh_lo);
    cudaGetSymbolAddress((void**)&attnh,  g_attnh);
    cudaGetSymbolAddress((void**)&woT_hi, g_woTh_hi);
    cudaGetSymbolAddress((void**)&woT_lo, g_woTh_lo);

    const int SM_DENSE  = 3 * 24576;   // <1,1,128,...>: A 8KB + B 16KB per stage
    const int SM_SCORES = 3 * 32768;   // <0,2,128,...>
    const int SM_AV     = 3 * 24576;   // <0,2,64,...>

    static int smem_set = 0;
    if (!smem_set) {
        cudaFuncSetAttribute(hgemm_kernel<1, 1, 128, 0, 0, 0>,
                             cudaFuncAttributeMaxDynamicSharedMemorySize, SM_DENSE);
        cudaFuncSetAttribute(hgemm_kernel<0, 2, 128, 1, 0, 0>,
                             cudaFuncAttributeMaxDynamicSharedMemorySize, SM_SCORES);
        cudaFuncSetAttribute(hgemm_kernel<0, 2, 64, 0, 1, 1>,
                             cudaFuncAttributeMaxDynamicSharedMemorySize, SM_AV);
        smem_set = 1;
    }

    const int M = Bq * Lq;           // 2048
    const int TH = 3 * Hq * Dq;      // 3072

    // 0) DAPE tables
    dape_pre_kernel<<<1024, 32>>>(w1, b1, log_p, log_a, kc, ktab);

    // 1) conversions for qkv GEMM (x single fp16; w_qkv^T split fp16)
    conv_half_kernel<<<(M * HIDq) / 256, 256>>>(x, xh, M * HIDq);
    conv_split_trans_h<<<dim3(TH / 32, HIDq / 32), dim3(32, 8)>>>(
        w_qkv, wqT_hi, wqT_lo, HIDq, TH);

    // 2) qkv = x @ w_qkv (fp16 2-term tensor cores)
    hgemm_kernel<1, 1, 128, 0, 0, 0><<<dim3(TH / 128, M / 128), 256, SM_DENSE>>>(
        xh, nullptr, wqT_hi, wqT_lo, qkv, nullptr,
        M, TH, HIDq, HIDq, HIDq, TH, 0, 0, 0, 1.0f);

    // 3) split + RoPE -> bf16 hi/lo q,k + transposed v
    rope_split_kernel<<<Bq * Hq * (Lq / 32), 256>>>(qkv, qhi, qlo, khi, klo, vThi, vTlo);

    // 4) scores = (q @ k^T)/8, batched 32, causal tile skip (bf16 3-term)
    hgemm_kernel<0, 2, 128, 1, 0, 0><<<dim3(Lq / 128, Lq / 128, Bq * Hq), 256, SM_SCORES>>>(
        (const __half*)qhi, (const __half*)qlo, (const __half*)khi, (const __half*)klo,
        sc, nullptr,
        Lq, Lq, Dq, Dq, Dq, Lq,
        (long long)Lq * Dq, (long long)Lq * Dq, (long long)Lq * Lq, 0.125f);

    // 5) fused kerple + DAPE MLP + causal softmax -> bf16 hi/lo weights
    dape_softmax_kernel<<<Bq * Lq, 1024>>>(sc, whi, wlo, w1, w2, b2, kc, ktab);

    // 6) attn = weights @ v (bf16 3-term, causal-K, fp16 out in (B,L,H*D))
    hgemm_kernel<0, 2, 64, 0, 1, 1><<<dim3(1, Lq / 128, Bq * Hq), 256, SM_AV>>>(
        (const __half*)whi, (const __half*)wlo, (const __half*)vThi, (const __half*)vTlo,
        nullptr, attnh,
        Lq, Dq, Lq, Lq, Lq, HIDq,
        (long long)Lq * Lq, (long long)Dq * Lq, 0, 1.0f);

    // 7) out = attn @ w_o (fp16 2-term tensor cores)
    conv_split_trans_h<<<dim3(HIDq / 32, HIDq / 32), dim3(32, 8)>>>(
        w_o, woT_hi, woT_lo, HIDq, HIDq);
    hgemm_kernel<1, 1, 128, 0, 0, 0><<<dim3(HIDq / 128, M / 128), 256, SM_DENSE>>>(
        attnh, nullptr, woT_hi, woT_lo, out, nullptr,
        M, HIDq, HIDq, HIDq, HIDq, HIDq, 0, 0, 0, 1.0f);
}

// round 12
// speedup vs baseline: 1.2824x; 1.0808x over previous
#include <cuda_runtime.h>
#include <cuda_bf16.h>
#include <cuda_fp16.h>
#include <math.h>

#define Bq   2
#define Lq   1024
#define Hq   16
#define Dq   64
#define HIDq 1024

typedef unsigned long long ull;

// ---------------- scratch (static device globals; no runtime alloc) ----------
__device__ float g_qkv[Bq * Lq * 3 * Hq * Dq];                  // (B,L,3,H,D)
__device__ float g_sc[(long long)Bq * Hq * Lq * Lq];            // (B,H,L,L) fp32 scores

__device__ __half g_qh[Bq * Hq * Lq * Dq];                            // q single fp16
__device__ __half g_khh[Bq * Hq * Lq * Dq], g_khl[Bq * Hq * Lq * Dq]; // k hi/lo
__device__ __half g_vThh[Bq * Hq * Dq * Lq], g_vThl[Bq * Hq * Dq * Lq]; // vT hi/lo
__device__ __half g_wh[(long long)Bq * Hq * Lq * Lq];                 // weights single fp16

__device__ __half g_xh[2048 * 1024];
__device__ __half g_wqkvTh_hi[3072 * 1024], g_wqkvTh_lo[3072 * 1024];
__device__ __half g_attnh[2048 * 1024];                               // (B,L,H*D)
__device__ __half g_woTh_hi[1024 * 1024], g_woTh_lo[1024 * 1024];

// DAPE precomputed tables
__device__ float g_kc[32 * 1024];     // [o][dist]
__device__ float g_ktab[16 * 1024];   // [h][dist]

// ---------------- f32x2 packed helpers ---------------------------------------
__device__ __forceinline__ ull pk2(float lo, float hi) {
    ull r; asm("mov.b64 %0,{%1,%2};" : "=l"(r) : "f"(lo), "f"(hi)); return r;
}
__device__ __forceinline__ void upk2(ull v, float& lo, float& hi) {
    asm("mov.b64 {%0,%1},%2;" : "=f"(lo), "=f"(hi) : "l"(v));
}
__device__ __forceinline__ ull ffma2(ull a, ull b, ull c) {
    ull d; asm("fma.rn.f32x2 %0,%1,%2,%3;" : "=l"(d) : "l"(a), "l"(b), "l"(c));
    return d;
}

// ======================= split fp16 tensor-core GEMM ========================
#define BM 128
#define BK 32
#define NSTG 3

__device__ __forceinline__ void ldm_x4(unsigned r[4], unsigned addr) {
    asm volatile("ldmatrix.sync.aligned.m8n8.x4.shared.b16 {%0,%1,%2,%3}, [%4];"
        : "=r"(r[0]), "=r"(r[1]), "=r"(r[2]), "=r"(r[3]) : "r"(addr));
}
__device__ __forceinline__ void mma16816h(float c[4], const unsigned a[4],
                                          unsigned b0, unsigned b1) {
    asm volatile("mma.sync.aligned.m16n8k16.row.col.f32.f16.f16.f32 "
        "{%0,%1,%2,%3},{%4,%5,%6,%7},{%8,%9},{%0,%1,%2,%3};"
        : "+f"(c[0]), "+f"(c[1]), "+f"(c[2]), "+f"(c[3])
        : "r"(a[0]), "r"(a[1]), "r"(a[2]), "r"(a[3]), "r"(b0), "r"(b1));
}
__device__ __forceinline__ void cp16(unsigned saddr, const void* g) {
    asm volatile("cp.async.cg.shared.global [%0], [%1], 16;\n" :: "r"(saddr), "l"(g));
}

// C = alpha * A(M,K) x B(N,K)^T.  A single fp16, B split hi/lo fp16 -> 2 passes.
// CJ: causal output-tile skip. CK: clamp K at bi+BM. OUT: 0 fp32 C, 1 fp16 C.
template <int BN_, int CJ, int CK, int OUT>
__global__ __launch_bounds__(256)
void hgemm_kernel(const __half* __restrict__ A,
                  const __half* __restrict__ Bhi, const __half* __restrict__ Blo,
                  float* __restrict__ Cf, __half* __restrict__ Ch,
                  int M, int N, int K, int lda, int ldb, int ldc,
                  long long sA, long long sB, long long sC, float alpha)
{
    constexpr int WCOL = BN_ / 4;
    constexpr int NT = WCOL / 16;
    constexpr unsigned BOFF = 8192u;
    constexpr unsigned BLOF = 8192u + BN_ * 64u;
    constexpr unsigned STG  = 8192u + BN_ * 128u;

    const int bz = blockIdx.z;
    A   += (long long)bz * sA;
    Bhi += (long long)bz * sB;  Blo += (long long)bz * sB;

    const int bi = blockIdx.y * BM, bj = blockIdx.x * BN_;
    if (CJ && bj > bi + BM - 1) return;

    extern __shared__ __half smem[];
    const unsigned sgen = (unsigned)__cvta_generic_to_shared(smem);
    const int tid = threadIdx.x;
    const int wid = tid >> 5, lane = tid & 31;
    const int wm = wid >> 2, wn = wid & 3;

    float acc[4][2 * NT][4];
    #pragma unroll
    for (int a = 0; a < 4; a++)
        #pragma unroll
        for (int b = 0; b < 2 * NT; b++)
            #pragma unroll
            for (int c = 0; c < 4; c++) acc[a][b][c] = 0.f;

    const int kmax = CK ? (bi + BM < K ? bi + BM : K) : K;
    const int nkt = kmax / BK;

    auto load_stage = [&](int stage, int kt) {
        int k0 = kt * BK;
        unsigned sb = sgen + stage * STG;
        #pragma unroll
        for (int t = tid; t < 512; t += 256) {          // A: 128 rows x 4 chunks
            int row = t >> 2, kc = t & 3;
            unsigned swc = (unsigned)(kc ^ ((row >> 1) & 3));
            unsigned so = sb + (unsigned)row * 64u + swc * 16u;
            cp16(so, A + (size_t)(bi + row) * lda + k0 + kc * 8);
        }
        #pragma unroll
        for (int t = tid; t < BN_ * 4; t += 256) {      // B: BN_ rows x 4 chunks
            int row = t >> 2, kc = t & 3;
            unsigned swc = (unsigned)(kc ^ ((row >> 1) & 3));
            unsigned so = sb + (unsigned)row * 64u + swc * 16u;
            cp16(so + BOFF, Bhi + (size_t)(bj + row) * ldb + k0 + kc * 8);
            cp16(so + BLOF, Blo + (size_t)(bj + row) * ldb + k0 + kc * 8);
        }
    };

    auto compute_stage = [&](int stage) {
        unsigned sb = sgen + stage * STG;
        #pragma unroll
        for (int ks = 0; ks < 2; ks++) {
            int r = lane & 15;
            int cc = ks * 2 + (lane >> 4);
            unsigned a_r[4][4];
            #pragma unroll
            for (int mt = 0; mt < 4; mt++) {
                int row = wm * 64 + mt * 16 + r;
                unsigned swc = (unsigned)(cc ^ ((row >> 1) & 3));
                ldm_x4(a_r[mt], sb + (unsigned)row * 64u + swc * 16u);
            }
            unsigned b_hi[NT][4], b_lo[NT][4];
            #pragma unroll
            for (int bt = 0; bt < NT; bt++) {
                int row = wn * WCOL + bt * 16 + r;
                unsigned swc = (unsigned)(cc ^ ((row >> 1) & 3));
                unsigned addr = sb + BOFF + (unsigned)row * 64u + swc * 16u;
                ldm_x4(b_hi[bt], addr);
                ldm_x4(b_lo[bt], addr + (BN_ * 64u));
            }
            #pragma unroll
            for (int mt = 0; mt < 4; mt++)
                #pragma unroll
                for (int n = 0; n < 2 * NT; n++) {
                    int bt = n >> 1, sel = n & 1;
                    mma16816h(acc[mt][n], a_r[mt], b_hi[bt][sel], b_hi[bt][sel + 2]);
                }
            #pragma unroll
            for (int mt = 0; mt < 4; mt++)
                #pragma unroll
                for (int n = 0; n < 2 * NT; n++) {
                    int bt = n >> 1, sel = n & 1;
                    mma16816h(acc[mt][n], a_r[mt], b_lo[bt][sel], b_lo[bt][sel + 2]);
                }
        }
    };

    #pragma unroll
    for (int s = 0; s < NSTG - 1; s++) {
        if (s < nkt) load_stage(s, s);
        asm volatile("cp.async.commit_group;\n");
    }
    for (int kt = 0; kt < nkt; kt++) {
        asm volatile("cp.async.wait_group %0;\n" :: "n"(NSTG - 2));
        __syncthreads();
        int kn = kt + NSTG - 1;
        if (kn < nkt) load_stage(kn % NSTG, kn);
        asm volatile("cp.async.commit_group;\n");
        compute_stage(kt % NSTG);
    }

    #pragma unroll
    for (int mt = 0; mt < 4; mt++) {
        int r0 = bi + wm * 64 + mt * 16 + (lane >> 2);
        #pragma unroll
        for (int n = 0; n < 2 * NT; n++) {
            int col = bj + wn * WCOL + (n >> 1) * 16 + (n & 1) * 8 + 2 * (lane & 3);
            if (OUT == 0) {
                float* C = Cf + (long long)bz * sC;
                float2 v0 = {alpha * acc[mt][n][0], alpha * acc[mt][n][1]};
                float2 v1 = {alpha * acc[mt][n][2], alpha * acc[mt][n][3]};
                *(float2*)&C[(size_t)r0 * ldc + col] = v0;
                *(float2*)&C[(size_t)(r0 + 8) * ldc + col] = v1;
            } else {
                long long base = (long long)(bz >> 4) * ((long long)Lq * HIDq)
                               + (long long)(bz & 15) * Dq;
                #pragma unroll
                for (int rr = 0; rr < 2; rr++) {
                    __half2 hv = __floats2half2_rn(acc[mt][n][rr * 2],
                                                   acc[mt][n][rr * 2 + 1]);
                    size_t off = base + (size_t)(r0 + rr * 8) * ldc + col;
                    *(__half2*)&Ch[off] = hv;
                }
            }
        }
    }
}

// ---------------- conversion kernels -----------------------------------------
__global__ void conv_half_kernel(const float* __restrict__ src,
                                 __half* __restrict__ dst, int n)
{
    int i = blockIdx.x * blockDim.x + threadIdx.x;
    if (i < n) dst[i] = __float2half(src[i]);
}

// W (K,N) fp32 row-major -> fp16 hi/lo (N,K) row-major (transposed)
__global__ void conv_split_trans_h(const float* __restrict__ W,
                                   __half* __restrict__ hi, __half* __restrict__ lo,
                                   int K, int N)
{
    __shared__ float t[32][33];
    int k0 = blockIdx.y * 32, n0 = blockIdx.x * 32;
    int tx = threadIdx.x, ty = threadIdx.y;
    #pragma unroll
    for (int r = ty; r < 32; r += 8)
        t[r][tx] = W[(size_t)(k0 + r) * N + n0 + tx];
    __syncthreads();
    #pragma unroll
    for (int r = ty; r < 32; r += 8) {
        float v = t[tx][r];
        __half h = __float2half(v);
        hi[(size_t)(n0 + r) * K + k0 + tx] = h;
        lo[(size_t)(n0 + r) * K + k0 + tx] = __float2half(v - __half2float(h));
    }
}

// ---------------- qkv split + RoPE -> fp16 q + k hi/lo + transposed v -------
__global__ __launch_bounds__(256)
void rope_split_kernel(const float* __restrict__ qkv,
                       __half* __restrict__ qh,
                       __half* __restrict__ khh, __half* __restrict__ khl,
                       __half* __restrict__ vThh, __half* __restrict__ vThl)
{
    __shared__ float sv[32][65];
    int bid = blockIdx.x;
    int l0 = (bid & 31) * 32;
    int h = (bid >> 5) & 15;
    int b = bid >> 9;
    int tid = threadIdx.x;

    #pragma unroll
    for (int e = 0; e < 8; e++) {
        int idx = tid + e * 256;
        int d = idx & 63, lr = idx >> 6;
        int l = l0 + lr;
        long long base = ((long long)(b * Lq + l) * 3) * (Hq * Dq) + h * Dq;
        float qa = qkv[base + d];
        float ka = qkv[base + Hq * Dq + d];
        float vv = qkv[base + 2 * Hq * Dq + d];
        int dp = (d < 32) ? d + 32 : d - 32;
        float qb = qkv[base + dp];
        float kb = qkv[base + Hq * Dq + dp];

        int fi = (d < 32) ? d : d - 32;
        float ang = (float)l * powf(10000.0f, -(float)fi / 32.0f);
        float c = cosf(ang), s = sinf(ang);
        float sgn = (d < 32) ? -1.0f : 1.0f;

        float qv = qa * c + sgn * qb * s;
        float kv = ka * c + sgn * kb * s;

        long long o = ((long long)(b * Hq + h) * Lq + l) * Dq + d;
        qh[o] = __float2half(qv);
        __half kh = __float2half(kv);
        khh[o] = kh;
        khl[o] = __float2half(kv - __half2float(kh));
        sv[lr][d] = vv;
    }
    __syncthreads();
    #pragma unroll
    for (int e = 0; e < 8; e++) {
        int idx = tid + e * 256;
        int lr = idx & 31, d = idx >> 5;
        float vv = sv[lr][d];
        __half vh = __float2half(vv);
        long long o = ((long long)(b * Hq + h) * Dq + d) * Lq + l0 + lr;
        vThh[o] = vh;
        vThl[o] = __float2half(vv - __half2float(vh));
    }
}

// ---------------- DAPE tables: kc[o][dist], ktab[h][dist] --------------------
__global__ void dape_pre_kernel(const float* __restrict__ w1, const float* __restrict__ b1,
                                const float* __restrict__ log_p, const float* __restrict__ log_a,
                                float* __restrict__ kc_t, float* __restrict__ ktab_t)
{
    int dist = blockIdx.x;
    int t = threadIdx.x;    // 32
    __shared__ float kv[16];
    if (t < 16) {
        float p = log1pf(expf(log_p[t]));
        float a = log1pf(expf(log_a[t]));
        float kvv = -p * log1pf(a * (float)dist);
        kv[t] = kvv;
        ktab_t[t * 1024 + dist] = kvv;
    }
    __syncthreads();
    float acc = b1[t];
    #pragma unroll
    for (int h = 0; h < 16; h++) acc += kv[h] * w1[(16 + h) * 32 + t];
    kc_t[t * 1024 + dist] = acc;
}

// ---------------- fused DAPE MLP + kerple + causal softmax (f32x2) ----------
__global__ __launch_bounds__(1024, 1)
void dape_softmax_kernel(const float* __restrict__ scores,
                         __half* __restrict__ wh,
                         const float* __restrict__ w1, const float* __restrict__ w2,
                         const float* __restrict__ b2,
                         const float* __restrict__ kc_t, const float* __restrict__ ktab_t)
{
    __shared__ ull s_w1p[32 * 8];
    __shared__ ull s_w2p[32 * 8];
    __shared__ float s_b2[16];
    __shared__ float s_red[16 * 32];
    __shared__ float s_bc[16];

    int tid = threadIdx.x;
    int i = blockIdx.x & (Lq - 1);
    int b = blockIdx.x >> 10;

    if (tid < 256) {
        int o = tid >> 3, p = tid & 7;
        s_w1p[o * 8 + p] = pk2(w1[(2 * p) * 32 + o], w1[(2 * p + 1) * 32 + o]);
        s_w2p[o * 8 + p] = pk2(w2[o * 16 + 2 * p], w2[o * 16 + 2 * p + 1]);
    }
    if (tid < 16) s_b2[tid] = b2[tid];
    __syncthreads();

    long long base0 = (long long)b * (Hq * Lq * Lq) + (long long)i * Lq;
    int j = tid;
    ull out2[8];

    if (j <= i) {
        int dist = i - j;
        ull s2[8];
        #pragma unroll
        for (int p = 0; p < 8; p++) {
            float s0 = scores[base0 + (long long)(2 * p)     * (Lq * Lq) + j];
            float s1 = scores[base0 + (long long)(2 * p + 1) * (Lq * Lq) + j];
            s2[p] = pk2(s0, s1);
            float k0 = ktab_t[(2 * p) * 1024 + dist];
            float k1 = ktab_t[(2 * p + 1) * 1024 + dist];
            out2[p] = pk2(s0 + k0 + s_b2[2 * p], s1 + k1 + s_b2[2 * p + 1]);
        }
        #pragma unroll 4
        for (int o = 0; o < 32; o++) {
            ull acc2 = pk2(kc_t[o * 1024 + dist], 0.0f);
            #pragma unroll
            for (int p = 0; p < 8; p++) acc2 = ffma2(s2[p], s_w1p[o * 8 + p], acc2);
            float a0, a1; upk2(acc2, a0, a1);
            float acc = a0 + a1;
            float u = 0.7978845608f * (acc + 0.044715f * acc * acc * acc);
            float th; asm("tanh.approx.f32 %0,%1;" : "=f"(th) : "f"(u));
            float g = 0.5f * acc * (1.0f + th);
            ull g2 = pk2(g, g);
            #pragma unroll
            for (int p = 0; p < 8; p++) out2[p] = ffma2(g2, s_w2p[o * 8 + p], out2[p]);
        }
    } else {
        #pragma unroll
        for (int p = 0; p < 8; p++) out2[p] = pk2(-INFINITY, -INFINITY);
    }

    int warp = tid >> 5, ln = tid & 31;

    #pragma unroll
    for (int p = 0; p < 8; p++) {
        float v0, v1; upk2(out2[p], v0, v1);
        #pragma unroll
        for (int off = 16; off > 0; off >>= 1) {
            v0 = fmaxf(v0, __shfl_xor_sync(0xffffffffu, v0, off));
            v1 = fmaxf(v1, __shfl_xor_sync(0xffffffffu, v1, off));
        }
        if (ln == 0) { s_red[(2 * p) * 32 + warp] = v0; s_red[(2 * p + 1) * 32 + warp] = v1; }
    }
    __syncthreads();
    if (tid < 16) {
        float v = s_red[tid * 32];
        #pragma unroll
        for (int w = 1; w < 32; w++) v = fmaxf(v, s_red[tid * 32 + w]);
        s_bc[tid] = v;
    }
    __syncthreads();

    #pragma unroll
    for (int p = 0; p < 8; p++) {
        float v0, v1; upk2(out2[p], v0, v1);
        v0 = __expf(v0 - s_bc[2 * p]);
        v1 = __expf(v1 - s_bc[2 * p + 1]);
        out2[p] = pk2(v0, v1);
    }
    __syncthreads();
    #pragma unroll
    for (int p = 0; p < 8; p++) {
        float v0, v1; upk2(out2[p], v0, v1);
        #pragma unroll
        for (int off = 16; off > 0; off >>= 1) {
            v0 += __shfl_xor_sync(0xffffffffu, v0, off);
            v1 += __shfl_xor_sync(0xffffffffu, v1, off);
        }
        if (ln == 0) { s_red[(2 * p) * 32 + warp] = v0; s_red[(2 * p + 1) * 32 + warp] = v1; }
    }
    __syncthreads();
    if (tid < 16) {
        float v = 0.0f;
        #pragma unroll
        for (int w = 0; w < 32; w++) v += s_red[tid * 32 + w];
        s_bc[tid] = 1.0f / v;
    }
    __syncthreads();

    #pragma unroll
    for (int p = 0; p < 8; p++) {
        float v0, v1; upk2(out2[p], v0, v1);
        long long off0 = base0 + (long long)(2 * p) * (Lq * Lq) + j;
        long long off1 = base0 + (long long)(2 * p + 1) * (Lq * Lq) + j;
        wh[off0] = __float2half(v0 * s_bc[2 * p]);
        wh[off1] = __float2half(v1 * s_bc[2 * p + 1]);
    }
}

// ---------------- launch ----------------------------------------------------
extern "C" void kernel_launch(void* const* d_in, const int* in_sizes, int n_in,
                              void* d_out, int out_size)
{
    const float* x     = (const float*)d_in[0];
    const float* w_qkv = (const float*)d_in[1];
    const float* w_o   = (const float*)d_in[2];
    const float* log_p = (const float*)d_in[3];
    const float* log_a = (const float*)d_in[4];
    const float* w1    = (const float*)d_in[5];
    const float* b1    = (const float*)d_in[6];
    const float* w2    = (const float*)d_in[7];
    const float* b2    = (const float*)d_in[8];
    float* out = (float*)d_out;
    (void)in_sizes; (void)n_in; (void)out_size;

    float *qkv, *sc, *kc, *ktab;
    __half *qh, *khh, *khl, *vThh, *vThl, *wh;
    __half *xh, *wqT_hi, *wqT_lo, *attnh, *woT_hi, *woT_lo;
    cudaGetSymbolAddress((void**)&qkv,  g_qkv);
    cudaGetSymbolAddress((void**)&sc,   g_sc);
    cudaGetSymbolAddress((void**)&kc,   g_kc);
    cudaGetSymbolAddress((void**)&ktab, g_ktab);
    cudaGetSymbolAddress((void**)&qh,   g_qh);
    cudaGetSymbolAddress((void**)&khh,  g_khh);
    cudaGetSymbolAddress((void**)&khl,  g_khl);
    cudaGetSymbolAddress((void**)&vThh, g_vThh);
    cudaGetSymbolAddress((void**)&vThl, g_vThl);
    cudaGetSymbolAddress((void**)&wh,   g_wh);
    cudaGetSymbolAddress((void**)&xh,     g_xh);
    cudaGetSymbolAddress((void**)&wqT_hi, g_wqkvTh_hi);
    cudaGetSymbolAddress((void**)&wqT_lo, g_wqkvTh_lo);
    cudaGetSymbolAddress((void**)&attnh,  g_attnh);
    cudaGetSymbolAddress((void**)&woT_hi, g_woTh_hi);
    cudaGetSymbolAddress((void**)&woT_lo, g_woTh_lo);

    const int SM_DENSE  = 3 * 24576;   // <128>: A 8KB + B 16KB per stage
    const int SM_SCORES = 3 * 24576;   // <128>
    const int SM_AV     = 3 * 16384;   // <64>: A 8KB + B 8KB per stage

    static int smem_set = 0;
    if (!smem_set) {
        cudaFuncSetAttribute(hgemm_kernel<128, 0, 0, 0>,
                             cudaFuncAttributeMaxDynamicSharedMemorySize, SM_DENSE);
        cudaFuncSetAttribute(hgemm_kernel<128, 1, 0, 0>,
                             cudaFuncAttributeMaxDynamicSharedMemorySize, SM_SCORES);
        cudaFuncSetAttribute(hgemm_kernel<64, 0, 1, 1>,
                             cudaFuncAttributeMaxDynamicSharedMemorySize, SM_AV);
        smem_set = 1;
    }

    const int M = Bq * Lq;           // 2048
    const int TH = 3 * Hq * Dq;      // 3072

    // 0) DAPE tables
    dape_pre_kernel<<<1024, 32>>>(w1, b1, log_p, log_a, kc, ktab);

    // 1) conversions for qkv GEMM (x single fp16; w_qkv^T split fp16)
    conv_half_kernel<<<(M * HIDq) / 256, 256>>>(x, xh, M * HIDq);
    conv_split_trans_h<<<dim3(TH / 32, HIDq / 32), dim3(32, 8)>>>(
        w_qkv, wqT_hi, wqT_lo, HIDq, TH);

    // 2) qkv = x @ w_qkv (fp16 2-term)
    hgemm_kernel<128, 0, 0, 0><<<dim3(TH / 128, M / 128), 256, SM_DENSE>>>(
        xh, wqT_hi, wqT_lo, qkv, nullptr,
        M, TH, HIDq, HIDq, HIDq, TH, 0, 0, 0, 1.0f);

    // 3) split + RoPE -> fp16 q single + k hi/lo + transposed v hi/lo
    rope_split_kernel<<<Bq * Hq * (Lq / 32), 256>>>(qkv, qh, khh, khl, vThh, vThl);

    // 4) scores = (q @ k^T)/8, batched 32, causal tile skip (fp16 2-term)
    hgemm_kernel<128, 1, 0, 0><<<dim3(Lq / 128, Lq / 128, Bq * Hq), 256, SM_SCORES>>>(
        qh, khh, khl, sc, nullptr,
        Lq, Lq, Dq, Dq, Dq, Lq,
        (long long)Lq * Dq, (long long)Lq * Dq, (long long)Lq * Lq, 0.125f);

    // 5) fused kerple + DAPE MLP + causal softmax -> fp16 weights
    dape_softmax_kernel<<<Bq * Lq, 1024>>>(sc, wh, w1, w2, b2, kc, ktab);

    // 6) attn = weights @ v (fp16 2-term, causal-K, fp16 out in (B,L,H*D))
    hgemm_kernel<64, 0, 1, 1><<<dim3(1, Lq / 128, Bq * Hq), 256, SM_AV>>>(
        wh, vThh, vThl, nullptr, attnh,
        Lq, Dq, Lq, Lq, Lq, HIDq,
        (long long)Lq * Lq, (long long)Dq * Lq, 0, 1.0f);

    // 7) out = attn @ w_o (fp16 2-term)
    conv_split_trans_h<<<dim3(HIDq / 32, HIDq / 32), dim3(32, 8)>>>(
        w_o, woT_hi, woT_lo, HIDq, HIDq);
    hgemm_kernel<128, 0, 0, 0><<<dim3(HIDq / 128, M / 128), 256, SM_DENSE>>>(
        attnh, woT_hi, woT_lo, out, nullptr,
        M, HIDq, HIDq, HIDq, HIDq, HIDq, 0, 0, 0, 1.0f);
}

// round 13
// speedup vs baseline: 1.2998x; 1.0136x over previous
#include <cuda_runtime.h>
#include <cuda_bf16.h>
#include <cuda_fp16.h>
#include <math.h>

#define Bq   2
#define Lq   1024
#define Hq   16
#define Dq   64
#define HIDq 1024

typedef unsigned long long ull;

// ---------------- scratch (static device globals; no runtime alloc) ----------
__device__ float  g_qkv[Bq * Lq * 3 * Hq * Dq];                 // (B,L,3,H,D)
__device__ __half g_sch[(long long)Bq * Hq * Lq * Lq];          // (B,H,L,L) fp16 scores

__device__ __half g_qh[Bq * Hq * Lq * Dq];                            // q single fp16
__device__ __half g_khh[Bq * Hq * Lq * Dq], g_khl[Bq * Hq * Lq * Dq]; // k hi/lo
__device__ __half g_vThh[Bq * Hq * Dq * Lq], g_vThl[Bq * Hq * Dq * Lq]; // vT hi/lo
__device__ __half g_wh[(long long)Bq * Hq * Lq * Lq];                 // weights single fp16

__device__ __half g_xh[2048 * 1024];
__device__ __half g_wqkvTh_hi[3072 * 1024], g_wqkvTh_lo[3072 * 1024];
__device__ __half g_attnh[2048 * 1024];                               // (B,L,H*D)
__device__ __half g_woTh_hi[1024 * 1024], g_woTh_lo[1024 * 1024];

// DAPE precomputed tables
__device__ float g_kc[32 * 1024];     // [o][dist]
__device__ float g_ktab[16 * 1024];   // [h][dist]

// ---------------- f32x2 packed helpers ---------------------------------------
__device__ __forceinline__ ull pk2(float lo, float hi) {
    ull r; asm("mov.b64 %0,{%1,%2};" : "=l"(r) : "f"(lo), "f"(hi)); return r;
}
__device__ __forceinline__ void upk2(ull v, float& lo, float& hi) {
    asm("mov.b64 {%0,%1},%2;" : "=f"(lo), "=f"(hi) : "l"(v));
}
__device__ __forceinline__ ull ffma2(ull a, ull b, ull c) {
    ull d; asm("fma.rn.f32x2 %0,%1,%2,%3;" : "=l"(d) : "l"(a), "l"(b), "l"(c));
    return d;
}

// ======================= split fp16 tensor-core GEMM ========================
#define BM 128
#define BK 32

__device__ __forceinline__ void ldm_x4(unsigned r[4], unsigned addr) {
    asm volatile("ldmatrix.sync.aligned.m8n8.x4.shared.b16 {%0,%1,%2,%3}, [%4];"
        : "=r"(r[0]), "=r"(r[1]), "=r"(r[2]), "=r"(r[3]) : "r"(addr));
}
__device__ __forceinline__ void mma16816h(float c[4], const unsigned a[4],
                                          unsigned b0, unsigned b1) {
    asm volatile("mma.sync.aligned.m16n8k16.row.col.f32.f16.f16.f32 "
        "{%0,%1,%2,%3},{%4,%5,%6,%7},{%8,%9},{%0,%1,%2,%3};"
        : "+f"(c[0]), "+f"(c[1]), "+f"(c[2]), "+f"(c[3])
        : "r"(a[0]), "r"(a[1]), "r"(a[2]), "r"(a[3]), "r"(b0), "r"(b1));
}
__device__ __forceinline__ void cp16(unsigned saddr, const void* g) {
    asm volatile("cp.async.cg.shared.global [%0], [%1], 16;\n" :: "r"(saddr), "l"(g));
}

// C = alpha * A(M,K) x B(N,K)^T.  A single fp16, B split hi/lo fp16 -> 2 passes.
// CJ: causal output-tile skip. CK: clamp K at bi+BM.
// OUT: 0 = fp32 C (alpha, stride sC); 1 = fp16 attn layout; 2 = fp16 C (alpha, sC).
template <int BN_, int NSTG_, int CJ, int CK, int OUT>
__global__ __launch_bounds__(256)
void hgemm_kernel(const __half* __restrict__ A,
                  const __half* __restrict__ Bhi, const __half* __restrict__ Blo,
                  float* __restrict__ Cf, __half* __restrict__ Ch,
                  int M, int N, int K, int lda, int ldb, int ldc,
                  long long sA, long long sB, long long sC, float alpha)
{
    constexpr int WCOL = BN_ / 4;
    constexpr int NT = WCOL / 16;
    constexpr unsigned BOFF = 8192u;
    constexpr unsigned BLOF = 8192u + BN_ * 64u;
    constexpr unsigned STG  = 8192u + BN_ * 128u;

    const int bz = blockIdx.z;
    A   += (long long)bz * sA;
    Bhi += (long long)bz * sB;  Blo += (long long)bz * sB;

    const int bi = blockIdx.y * BM, bj = blockIdx.x * BN_;
    if (CJ && bj > bi + BM - 1) return;

    extern __shared__ __half smem[];
    const unsigned sgen = (unsigned)__cvta_generic_to_shared(smem);
    const int tid = threadIdx.x;
    const int wid = tid >> 5, lane = tid & 31;
    const int wm = wid >> 2, wn = wid & 3;

    float acc[4][2 * NT][4];
    #pragma unroll
    for (int a = 0; a < 4; a++)
        #pragma unroll
        for (int b = 0; b < 2 * NT; b++)
            #pragma unroll
            for (int c = 0; c < 4; c++) acc[a][b][c] = 0.f;

    const int kmax = CK ? (bi + BM < K ? bi + BM : K) : K;
    const int nkt = kmax / BK;

    auto load_stage = [&](int stage, int kt) {
        int k0 = kt * BK;
        unsigned sb = sgen + stage * STG;
        #pragma unroll
        for (int t = tid; t < 512; t += 256) {          // A: 128 rows x 4 chunks
            int row = t >> 2, kc = t & 3;
            unsigned swc = (unsigned)(kc ^ ((row >> 1) & 3));
            unsigned so = sb + (unsigned)row * 64u + swc * 16u;
            cp16(so, A + (size_t)(bi + row) * lda + k0 + kc * 8);
        }
        #pragma unroll
        for (int t = tid; t < BN_ * 4; t += 256) {      // B: BN_ rows x 4 chunks
            int row = t >> 2, kc = t & 3;
            unsigned swc = (unsigned)(kc ^ ((row >> 1) & 3));
            unsigned so = sb + (unsigned)row * 64u + swc * 16u;
            cp16(so + BOFF, Bhi + (size_t)(bj + row) * ldb + k0 + kc * 8);
            cp16(so + BLOF, Blo + (size_t)(bj + row) * ldb + k0 + kc * 8);
        }
    };

    auto compute_stage = [&](int stage) {
        unsigned sb = sgen + stage * STG;
        #pragma unroll
        for (int ks = 0; ks < 2; ks++) {
            int r = lane & 15;
            int cc = ks * 2 + (lane >> 4);
            unsigned a_r[4][4];
            #pragma unroll
            for (int mt = 0; mt < 4; mt++) {
                int row = wm * 64 + mt * 16 + r;
                unsigned swc = (unsigned)(cc ^ ((row >> 1) & 3));
                ldm_x4(a_r[mt], sb + (unsigned)row * 64u + swc * 16u);
            }
            unsigned b_hi[NT][4], b_lo[NT][4];
            #pragma unroll
            for (int bt = 0; bt < NT; bt++) {
                int row = wn * WCOL + bt * 16 + r;
                unsigned swc = (unsigned)(cc ^ ((row >> 1) & 3));
                unsigned addr = sb + BOFF + (unsigned)row * 64u + swc * 16u;
                ldm_x4(b_hi[bt], addr);
                ldm_x4(b_lo[bt], addr + (BN_ * 64u));
            }
            #pragma unroll
            for (int mt = 0; mt < 4; mt++)
                #pragma unroll
                for (int n = 0; n < 2 * NT; n++) {
                    int bt = n >> 1, sel = n & 1;
                    mma16816h(acc[mt][n], a_r[mt], b_hi[bt][sel], b_hi[bt][sel + 2]);
                }
            #pragma unroll
            for (int mt = 0; mt < 4; mt++)
                #pragma unroll
                for (int n = 0; n < 2 * NT; n++) {
                    int bt = n >> 1, sel = n & 1;
                    mma16816h(acc[mt][n], a_r[mt], b_lo[bt][sel], b_lo[bt][sel + 2]);
                }
        }
    };

    #pragma unroll
    for (int s = 0; s < NSTG_ - 1; s++) {
        if (s < nkt) load_stage(s, s);
        asm volatile("cp.async.commit_group;\n");
    }
    for (int kt = 0; kt < nkt; kt++) {
        asm volatile("cp.async.wait_group %0;\n" :: "n"(NSTG_ - 2));
        __syncthreads();
        int kn = kt + NSTG_ - 1;
        if (kn < nkt) load_stage(kn % NSTG_, kn);
        asm volatile("cp.async.commit_group;\n");
        compute_stage(kt % NSTG_);
    }

    #pragma unroll
    for (int mt = 0; mt < 4; mt++) {
        int r0 = bi + wm * 64 + mt * 16 + (lane >> 2);
        #pragma unroll
        for (int n = 0; n < 2 * NT; n++) {
            int col = bj + wn * WCOL + (n >> 1) * 16 + (n & 1) * 8 + 2 * (lane & 3);
            if (OUT == 0) {
                float* C = Cf + (long long)bz * sC;
                float2 v0 = {alpha * acc[mt][n][0], alpha * acc[mt][n][1]};
                float2 v1 = {alpha * acc[mt][n][2], alpha * acc[mt][n][3]};
                *(float2*)&C[(size_t)r0 * ldc + col] = v0;
                *(float2*)&C[(size_t)(r0 + 8) * ldc + col] = v1;
            } else if (OUT == 2) {
                __half* C = Ch + (long long)bz * sC;
                __half2 v0 = __floats2half2_rn(alpha * acc[mt][n][0], alpha * acc[mt][n][1]);
                __half2 v1 = __floats2half2_rn(alpha * acc[mt][n][2], alpha * acc[mt][n][3]);
                *(__half2*)&C[(size_t)r0 * ldc + col] = v0;
                *(__half2*)&C[(size_t)(r0 + 8) * ldc + col] = v1;
            } else {
                long long base = (long long)(bz >> 4) * ((long long)Lq * HIDq)
                               + (long long)(bz & 15) * Dq;
                #pragma unroll
                for (int rr = 0; rr < 2; rr++) {
                    __half2 hv = __floats2half2_rn(acc[mt][n][rr * 2],
                                                   acc[mt][n][rr * 2 + 1]);
                    size_t off = base + (size_t)(r0 + rr * 8) * ldc + col;
                    *(__half2*)&Ch[off] = hv;
                }
            }
        }
    }
}

// ---------------- conversion kernels -----------------------------------------
__global__ void conv_half_kernel(const float* __restrict__ src,
                                 __half* __restrict__ dst, int n)
{
    int i = blockIdx.x * blockDim.x + threadIdx.x;
    if (i < n) dst[i] = __float2half(src[i]);
}

// W (K,N) fp32 row-major -> fp16 hi/lo (N,K) row-major (transposed)
__global__ void conv_split_trans_h(const float* __restrict__ W,
                                   __half* __restrict__ hi, __half* __restrict__ lo,
                                   int K, int N)
{
    __shared__ float t[32][33];
    int k0 = blockIdx.y * 32, n0 = blockIdx.x * 32;
    int tx = threadIdx.x, ty = threadIdx.y;
    #pragma unroll
    for (int r = ty; r < 32; r += 8)
        t[r][tx] = W[(size_t)(k0 + r) * N + n0 + tx];
    __syncthreads();
    #pragma unroll
    for (int r = ty; r < 32; r += 8) {
        float v = t[tx][r];
        __half h = __float2half(v);
        hi[(size_t)(n0 + r) * K + k0 + tx] = h;
        lo[(size_t)(n0 + r) * K + k0 + tx] = __float2half(v - __half2float(h));
    }
}

// ---------------- qkv split + RoPE -> fp16 q + k hi/lo + transposed v -------
__global__ __launch_bounds__(256)
void rope_split_kernel(const float* __restrict__ qkv,
                       __half* __restrict__ qh,
                       __half* __restrict__ khh, __half* __restrict__ khl,
                       __half* __restrict__ vThh, __half* __restrict__ vThl)
{
    __shared__ float sv[32][65];
    int bid = blockIdx.x;
    int l0 = (bid & 31) * 32;
    int h = (bid >> 5) & 15;
    int b = bid >> 9;
    int tid = threadIdx.x;

    #pragma unroll
    for (int e = 0; e < 8; e++) {
        int idx = tid + e * 256;
        int d = idx & 63, lr = idx >> 6;
        int l = l0 + lr;
        long long base = ((long long)(b * Lq + l) * 3) * (Hq * Dq) + h * Dq;
        float qa = qkv[base + d];
        float ka = qkv[base + Hq * Dq + d];
        float vv = qkv[base + 2 * Hq * Dq + d];
        int dp = (d < 32) ? d + 32 : d - 32;
        float qb = qkv[base + dp];
        float kb = qkv[base + Hq * Dq + dp];

        int fi = (d < 32) ? d : d - 32;
        float ang = (float)l * powf(10000.0f, -(float)fi / 32.0f);
        float c = cosf(ang), s = sinf(ang);
        float sgn = (d < 32) ? -1.0f : 1.0f;

        float qv = qa * c + sgn * qb * s;
        float kv = ka * c + sgn * kb * s;

        long long o = ((long long)(b * Hq + h) * Lq + l) * Dq + d;
        qh[o] = __float2half(qv);
        __half kh = __float2half(kv);
        khh[o] = kh;
        khl[o] = __float2half(kv - __half2float(kh));
        sv[lr][d] = vv;
    }
    __syncthreads();
    #pragma unroll
    for (int e = 0; e < 8; e++) {
        int idx = tid + e * 256;
        int lr = idx & 31, d = idx >> 5;
        float vv = sv[lr][d];
        __half vh = __float2half(vv);
        long long o = ((long long)(b * Hq + h) * Dq + d) * Lq + l0 + lr;
        vThh[o] = vh;
        vThl[o] = __float2half(vv - __half2float(vh));
    }
}

// ---------------- DAPE tables: kc[o][dist], ktab[h][dist] --------------------
__global__ void dape_pre_kernel(const float* __restrict__ w1, const float* __restrict__ b1,
                                const float* __restrict__ log_p, const float* __restrict__ log_a,
                                float* __restrict__ kc_t, float* __restrict__ ktab_t)
{
    int dist = blockIdx.x;
    int t = threadIdx.x;    // 32
    __shared__ float kv[16];
    if (t < 16) {
        float p = log1pf(expf(log_p[t]));
        float a = log1pf(expf(log_a[t]));
        float kvv = -p * log1pf(a * (float)dist);
        kv[t] = kvv;
        ktab_t[t * 1024 + dist] = kvv;
    }
    __syncthreads();
    float acc = b1[t];
    #pragma unroll
    for (int h = 0; h < 16; h++) acc += kv[h] * w1[(16 + h) * 32 + t];
    kc_t[t * 1024 + dist] = acc;
}

// ---------------- fused DAPE MLP + kerple + causal softmax (f32x2) ----------
__global__ __launch_bounds__(1024, 1)
void dape_softmax_kernel(const __half* __restrict__ scores,
                         __half* __restrict__ wh,
                         const float* __restrict__ w1, const float* __restrict__ w2,
                         const float* __restrict__ b2,
                         const float* __restrict__ kc_t, const float* __restrict__ ktab_t)
{
    __shared__ ull s_w1p[32 * 8];
    __shared__ ull s_w2p[32 * 8];
    __shared__ float s_b2[16];
    __shared__ float s_red[16 * 32];
    __shared__ float s_bc[16];

    int tid = threadIdx.x;
    int i = blockIdx.x & (Lq - 1);
    int b = blockIdx.x >> 10;

    if (tid < 256) {
        int o = tid >> 3, p = tid & 7;
        s_w1p[o * 8 + p] = pk2(w1[(2 * p) * 32 + o], w1[(2 * p + 1) * 32 + o]);
        s_w2p[o * 8 + p] = pk2(w2[o * 16 + 2 * p], w2[o * 16 + 2 * p + 1]);
    }
    if (tid < 16) s_b2[tid] = b2[tid];
    __syncthreads();

    long long base0 = (long long)b * (Hq * Lq * Lq) + (long long)i * Lq;
    int j = tid;
    ull out2[8];

    if (j <= i) {
        int dist = i - j;
        ull s2[8];
        #pragma unroll
        for (int p = 0; p < 8; p++) {
            float s0 = __half2float(scores[base0 + (long long)(2 * p)     * (Lq * Lq) + j]);
            float s1 = __half2float(scores[base0 + (long long)(2 * p + 1) * (Lq * Lq) + j]);
            s2[p] = pk2(s0, s1);
            float k0 = ktab_t[(2 * p) * 1024 + dist];
            float k1 = ktab_t[(2 * p + 1) * 1024 + dist];
            out2[p] = pk2(s0 + k0 + s_b2[2 * p], s1 + k1 + s_b2[2 * p + 1]);
        }
        #pragma unroll 4
        for (int o = 0; o < 32; o++) {
            ull acc2 = pk2(kc_t[o * 1024 + dist], 0.0f);
            #pragma unroll
            for (int p = 0; p < 8; p++) acc2 = ffma2(s2[p], s_w1p[o * 8 + p], acc2);
            float a0, a1; upk2(acc2, a0, a1);
            float acc = a0 + a1;
            float u = 0.7978845608f * (acc + 0.044715f * acc * acc * acc);
            float th; asm("tanh.approx.f32 %0,%1;" : "=f"(th) : "f"(u));
            float g = 0.5f * acc * (1.0f + th);
            ull g2 = pk2(g, g);
            #pragma unroll
            for (int p = 0; p < 8; p++) out2[p] = ffma2(g2, s_w2p[o * 8 + p], out2[p]);
        }
    } else {
        #pragma unroll
        for (int p = 0; p < 8; p++) out2[p] = pk2(-INFINITY, -INFINITY);
    }

    int warp = tid >> 5, ln = tid & 31;

    #pragma unroll
    for (int p = 0; p < 8; p++) {
        float v0, v1; upk2(out2[p], v0, v1);
        #pragma unroll
        for (int off = 16; off > 0; off >>= 1) {
            v0 = fmaxf(v0, __shfl_xor_sync(0xffffffffu, v0, off));
            v1 = fmaxf(v1, __shfl_xor_sync(0xffffffffu, v1, off));
        }
        if (ln == 0) { s_red[(2 * p) * 32 + warp] = v0; s_red[(2 * p + 1) * 32 + warp] = v1; }
    }
    __syncthreads();
    if (tid < 16) {
        float v = s_red[tid * 32];
        #pragma unroll
        for (int w = 1; w < 32; w++) v = fmaxf(v, s_red[tid * 32 + w]);
        s_bc[tid] = v;
    }
    __syncthreads();

    #pragma unroll
    for (int p = 0; p < 8; p++) {
        float v0, v1; upk2(out2[p], v0, v1);
        v0 = __expf(v0 - s_bc[2 * p]);
        v1 = __expf(v1 - s_bc[2 * p + 1]);
        out2[p] = pk2(v0, v1);
    }
    __syncthreads();
    #pragma unroll
    for (int p = 0; p < 8; p++) {
        float v0, v1; upk2(out2[p], v0, v1);
        #pragma unroll
        for (int off = 16; off > 0; off >>= 1) {
            v0 += __shfl_xor_sync(0xffffffffu, v0, off);
            v1 += __shfl_xor_sync(0xffffffffu, v1, off);
        }
        if (ln == 0) { s_red[(2 * p) * 32 + warp] = v0; s_red[(2 * p + 1) * 32 + warp] = v1; }
    }
    __syncthreads();
    if (tid < 16) {
        float v = 0.0f;
        #pragma unroll
        for (int w = 0; w < 32; w++) v += s_red[tid * 32 + w];
        s_bc[tid] = 1.0f / v;
    }
    __syncthreads();

    #pragma unroll
    for (int p = 0; p < 8; p++) {
        float v0, v1; upk2(out2[p], v0, v1);
        long long off0 = base0 + (long long)(2 * p) * (Lq * Lq) + j;
        long long off1 = base0 + (long long)(2 * p + 1) * (Lq * Lq) + j;
        wh[off0] = __float2half(v0 * s_bc[2 * p]);
        wh[off1] = __float2half(v1 * s_bc[2 * p + 1]);
    }
}

// ---------------- launch ----------------------------------------------------
extern "C" void kernel_launch(void* const* d_in, const int* in_sizes, int n_in,
                              void* d_out, int out_size)
{
    const float* x     = (const float*)d_in[0];
    const float* w_qkv = (const float*)d_in[1];
    const float* w_o   = (const float*)d_in[2];
    const float* log_p = (const float*)d_in[3];
    const float* log_a = (const float*)d_in[4];
    const float* w1    = (const float*)d_in[5];
    const float* b1    = (const float*)d_in[6];
    const float* w2    = (const float*)d_in[7];
    const float* b2    = (const float*)d_in[8];
    float* out = (float*)d_out;
    (void)in_sizes; (void)n_in; (void)out_size;

    float *qkv, *kc, *ktab;
    __half *sch, *qh, *khh, *khl, *vThh, *vThl, *wh;
    __half *xh, *wqT_hi, *wqT_lo, *attnh, *woT_hi, *woT_lo;
    cudaGetSymbolAddress((void**)&qkv,  g_qkv);
    cudaGetSymbolAddress((void**)&sch,  g_sch);
    cudaGetSymbolAddress((void**)&kc,   g_kc);
    cudaGetSymbolAddress((void**)&ktab, g_ktab);
    cudaGetSymbolAddress((void**)&qh,   g_qh);
    cudaGetSymbolAddress((void**)&khh,  g_khh);
    cudaGetSymbolAddress((void**)&khl,  g_khl);
    cudaGetSymbolAddress((void**)&vThh, g_vThh);
    cudaGetSymbolAddress((void**)&vThl, g_vThl);
    cudaGetSymbolAddress((void**)&wh,   g_wh);
    cudaGetSymbolAddress((void**)&xh,     g_xh);
    cudaGetSymbolAddress((void**)&wqT_hi, g_wqkvTh_hi);
    cudaGetSymbolAddress((void**)&wqT_lo, g_wqkvTh_lo);
    cudaGetSymbolAddress((void**)&attnh,  g_attnh);
    cudaGetSymbolAddress((void**)&woT_hi, g_woTh_hi);
    cudaGetSymbolAddress((void**)&woT_lo, g_woTh_lo);

    const int SM_DENSE  = 4 * 24576;   // <128, NSTG=4>
    const int SM_SCORES = 3 * 24576;   // <128, NSTG=3>
    const int SM_AV     = 3 * 16384;   // <64,  NSTG=3>

    static int smem_set = 0;
    if (!smem_set) {
        cudaFuncSetAttribute(hgemm_kernel<128, 4, 0, 0, 0>,
                             cudaFuncAttributeMaxDynamicSharedMemorySize, SM_DENSE);
        cudaFuncSetAttribute(hgemm_kernel<128, 3, 1, 0, 2>,
                             cudaFuncAttributeMaxDynamicSharedMemorySize, SM_SCORES);
        cudaFuncSetAttribute(hgemm_kernel<64, 3, 0, 1, 1>,
                             cudaFuncAttributeMaxDynamicSharedMemorySize, SM_AV);
        smem_set = 1;
    }

    const int M = Bq * Lq;           // 2048
    const int TH = 3 * Hq * Dq;      // 3072

    // 0) DAPE tables
    dape_pre_kernel<<<1024, 32>>>(w1, b1, log_p, log_a, kc, ktab);

    // 1) conversions for qkv GEMM (x single fp16; w_qkv^T split fp16)
    conv_half_kernel<<<(M * HIDq) / 256, 256>>>(x, xh, M * HIDq);
    conv_split_trans_h<<<dim3(TH / 32, HIDq / 32), dim3(32, 8)>>>(
        w_qkv, wqT_hi, wqT_lo, HIDq, TH);

    // 2) qkv = x @ w_qkv (fp16 2-term, 4-stage)
    hgemm_kernel<128, 4, 0, 0, 0><<<dim3(TH / 128, M / 128), 256, SM_DENSE>>>(
        xh, wqT_hi, wqT_lo, qkv, nullptr,
        M, TH, HIDq, HIDq, HIDq, TH, 0, 0, 0, 1.0f);

    // 3) split + RoPE -> fp16 q single + k hi/lo + transposed v hi/lo
    rope_split_kernel<<<Bq * Hq * (Lq / 32), 256>>>(qkv, qh, khh, khl, vThh, vThl);

    // 4) scores = (q @ k^T)/8, batched 32, causal tile skip -> fp16 planes
    hgemm_kernel<128, 3, 1, 0, 2><<<dim3(Lq / 128, Lq / 128, Bq * Hq), 256, SM_SCORES>>>(
        qh, khh, khl, nullptr, sch,
        Lq, Lq, Dq, Dq, Dq, Lq,
        (long long)Lq * Dq, (long long)Lq * Dq, (long long)Lq * Lq, 0.125f);

    // 5) fused kerple + DAPE MLP + causal softmax -> fp16 weights
    dape_softmax_kernel<<<Bq * Lq, 1024>>>(sch, wh, w1, w2, b2, kc, ktab);

    // 6) attn = weights @ v (fp16 2-term, causal-K, fp16 out in (B,L,H*D))
    hgemm_kernel<64, 3, 0, 1, 1><<<dim3(1, Lq / 128, Bq * Hq), 256, SM_AV>>>(
        wh, vThh, vThl, nullptr, attnh,
        Lq, Dq, Lq, Lq, Lq, HIDq,
        (long long)Lq * Lq, (long long)Dq * Lq, 0, 1.0f);

    // 7) out = attn @ w_o (fp16 2-term, 4-stage)
    conv_split_trans_h<<<dim3(HIDq / 32, HIDq / 32), dim3(32, 8)>>>(
        w_o, woT_hi, woT_lo, HIDq, HIDq);
    hgemm_kernel<128, 4, 0, 0, 0><<<dim3(HIDq / 128, M / 128), 256, SM_DENSE>>>(
        attnh, woT_hi, woT_lo, out, nullptr,
        M, HIDq, HIDq, HIDq, HIDq, HIDq, 0, 0, 0, 1.0f);
}

// round 16
// speedup vs baseline: 1.4962x; 1.1511x over previous
#include <cuda_runtime.h>
#include <cuda_fp16.h>
#include <math.h>

#define Bq   2
#define Lq   1024
#define Hq   16
#define Dq   64
#define HIDq 1024

typedef unsigned long long ull;

// ---------------- scratch (static device globals; no runtime alloc) ----------
__device__ float  g_qkv[Bq * Lq * 3 * Hq * Dq];                 // (B,L,3,H,D)
__device__ __half g_sch[(long long)Bq * Hq * Lq * Lq];          // (B,H,L,L) fp16 scores

__device__ __half g_qh[Bq * Hq * Lq * Dq];                      // q fp16
__device__ __half g_kh[Bq * Hq * Lq * Dq];                      // k fp16
__device__ __half g_vTh[Bq * Hq * Dq * Lq];                     // vT fp16 (B,H,D,L)
__device__ __half g_wh[(long long)Bq * Hq * Lq * Lq];           // weights fp16

__device__ __half g_xh[2048 * 1024];
__device__ __half g_wqkvTh[3072 * 1024];
__device__ __half g_attnh[2048 * 1024];                         // (B,L,H*D)
__device__ __half g_woTh[1024 * 1024];

// DAPE precomputed tables
__device__ float g_kc[32 * 1024];     // [o][dist]
__device__ float g_ktab[16 * 1024];   // [h][dist]

// ---------------- f32x2 packed helpers ---------------------------------------
__device__ __forceinline__ ull pk2(float lo, float hi) {
    ull r; asm("mov.b64 %0,{%1,%2};" : "=l"(r) : "f"(lo), "f"(hi)); return r;
}
__device__ __forceinline__ void upk2(ull v, float& lo, float& hi) {
    asm("mov.b64 {%0,%1},%2;" : "=f"(lo), "=f"(hi) : "l"(v));
}
__device__ __forceinline__ ull ffma2(ull a, ull b, ull c) {
    ull d; asm("fma.rn.f32x2 %0,%1,%2,%3;" : "=l"(d) : "l"(a), "l"(b), "l"(c));
    return d;
}

// ======================= fp16 tensor-core GEMM (single-pass) ================
#define BM 128
#define BK 32

__device__ __forceinline__ void ldm_x4(unsigned r[4], unsigned addr) {
    asm volatile("ldmatrix.sync.aligned.m8n8.x4.shared.b16 {%0,%1,%2,%3}, [%4];"
        : "=r"(r[0]), "=r"(r[1]), "=r"(r[2]), "=r"(r[3]) : "r"(addr));
}
__device__ __forceinline__ void mma16816h(float c[4], const unsigned a[4],
                                          unsigned b0, unsigned b1) {
    asm volatile("mma.sync.aligned.m16n8k16.row.col.f32.f16.f16.f32 "
        "{%0,%1,%2,%3},{%4,%5,%6,%7},{%8,%9},{%0,%1,%2,%3};"
        : "+f"(c[0]), "+f"(c[1]), "+f"(c[2]), "+f"(c[3])
        : "r"(a[0]), "r"(a[1]), "r"(a[2]), "r"(a[3]), "r"(b0), "r"(b1));
}
__device__ __forceinline__ void cp16(unsigned saddr, const void* g) {
    asm volatile("cp.async.cg.shared.global [%0], [%1], 16;\n" :: "r"(saddr), "l"(g));
}

// C = alpha * A(M,K) x B(N,K)^T, plain fp16 x fp16, fp32 accumulate.
// CJ: causal output-tile skip. CK: clamp K at bi+BM.
// OUT: 0 = fp32 C (alpha, stride sC); 1 = fp16 attn layout; 2 = fp16 C (alpha, sC).
template <int BN_, int NSTG_, int CJ, int CK, int OUT>
__global__ __launch_bounds__(256)
void hgemm_kernel(const __half* __restrict__ A, const __half* __restrict__ B,
                  float* __restrict__ Cf, __half* __restrict__ Ch,
                  int M, int N, int K, int lda, int ldb, int ldc,
                  long long sA, long long sB, long long sC, float alpha)
{
    constexpr int WCOL = BN_ / 4;
    constexpr int NT = WCOL / 16;
    constexpr unsigned BOFF = 8192u;
    constexpr unsigned STG  = 8192u + BN_ * 64u;

    const int bz = blockIdx.z;
    A += (long long)bz * sA;
    B += (long long)bz * sB;

    const int bi = blockIdx.y * BM, bj = blockIdx.x * BN_;
    if (CJ && bj > bi + BM - 1) return;

    extern __shared__ __half smem[];
    const unsigned sgen = (unsigned)__cvta_generic_to_shared(smem);
    const int tid = threadIdx.x;
    const int wid = tid >> 5, lane = tid & 31;
    const int wm = wid >> 2, wn = wid & 3;

    float acc[4][2 * NT][4];
    #pragma unroll
    for (int a = 0; a < 4; a++)
        #pragma unroll
        for (int b = 0; b < 2 * NT; b++)
            #pragma unroll
            for (int c = 0; c < 4; c++) acc[a][b][c] = 0.f;

    const int kmax = CK ? (bi + BM < K ? bi + BM : K) : K;
    const int nkt = kmax / BK;

    auto load_stage = [&](int stage, int kt) {
        int k0 = kt * BK;
        unsigned sb = sgen + stage * STG;
        #pragma unroll
        for (int t = tid; t < 512; t += 256) {          // A: 128 rows x 4 chunks
            int row = t >> 2, kc = t & 3;
            unsigned swc = (unsigned)(kc ^ ((row >> 1) & 3));
            unsigned so = sb + (unsigned)row * 64u + swc * 16u;
            cp16(so, A + (size_t)(bi + row) * lda + k0 + kc * 8);
        }
        #pragma unroll
        for (int t = tid; t < BN_ * 4; t += 256) {      // B: BN_ rows x 4 chunks
            int row = t >> 2, kc = t & 3;
            unsigned swc = (unsigned)(kc ^ ((row >> 1) & 3));
            unsigned so = sb + (unsigned)row * 64u + swc * 16u;
            cp16(so + BOFF, B + (size_t)(bj + row) * ldb + k0 + kc * 8);
        }
    };

    auto compute_stage = [&](int stage) {
        unsigned sb = sgen + stage * STG;
        #pragma unroll
        for (int ks = 0; ks < 2; ks++) {
            int r = lane & 15;
            int cc = ks * 2 + (lane >> 4);
            unsigned a_r[4][4];
            #pragma unroll
            for (int mt = 0; mt < 4; mt++) {
                int row = wm * 64 + mt * 16 + r;
                unsigned swc = (unsigned)(cc ^ ((row >> 1) & 3));
                ldm_x4(a_r[mt], sb + (unsigned)row * 64u + swc * 16u);
            }
            unsigned b_r[NT][4];
            #pragma unroll
            for (int bt = 0; bt < NT; bt++) {
                int row = wn * WCOL + bt * 16 + r;
                unsigned swc = (unsigned)(cc ^ ((row >> 1) & 3));
                ldm_x4(b_r[bt], sb + BOFF + (unsigned)row * 64u + swc * 16u);
            }
            #pragma unroll
            for (int mt = 0; mt < 4; mt++)
                #pragma unroll
                for (int n = 0; n < 2 * NT; n++) {
                    int bt = n >> 1, sel = n & 1;
                    mma16816h(acc[mt][n], a_r[mt], b_r[bt][sel], b_r[bt][sel + 2]);
                }
        }
    };

    #pragma unroll
    for (int s = 0; s < NSTG_ - 1; s++) {
        if (s < nkt) load_stage(s, s);
        asm volatile("cp.async.commit_group;\n");
    }
    for (int kt = 0; kt < nkt; kt++) {
        asm volatile("cp.async.wait_group %0;\n" :: "n"(NSTG_ - 2));
        __syncthreads();
        int kn = kt + NSTG_ - 1;
        if (kn < nkt) load_stage(kn % NSTG_, kn);
        asm volatile("cp.async.commit_group;\n");
        compute_stage(kt % NSTG_);
    }

    #pragma unroll
    for (int mt = 0; mt < 4; mt++) {
        int r0 = bi + wm * 64 + mt * 16 + (lane >> 2);
        #pragma unroll
        for (int n = 0; n < 2 * NT; n++) {
            int col = bj + wn * WCOL + (n >> 1) * 16 + (n & 1) * 8 + 2 * (lane & 3);
            if (OUT == 0) {
                float* C = Cf + (long long)bz * sC;
                float2 v0 = {alpha * acc[mt][n][0], alpha * acc[mt][n][1]};
                float2 v1 = {alpha * acc[mt][n][2], alpha * acc[mt][n][3]};
                *(float2*)&C[(size_t)r0 * ldc + col] = v0;
                *(float2*)&C[(size_t)(r0 + 8) * ldc + col] = v1;
            } else if (OUT == 2) {
                __half* C = Ch + (long long)bz * sC;
                __half2 v0 = __floats2half2_rn(alpha * acc[mt][n][0], alpha * acc[mt][n][1]);
                __half2 v1 = __floats2half2_rn(alpha * acc[mt][n][2], alpha * acc[mt][n][3]);
                *(__half2*)&C[(size_t)r0 * ldc + col] = v0;
                *(__half2*)&C[(size_t)(r0 + 8) * ldc + col] = v1;
            } else {
                long long base = (long long)(bz >> 4) * ((long long)Lq * HIDq)
                               + (long long)(bz & 15) * Dq;
                #pragma unroll
                for (int rr = 0; rr < 2; rr++) {
                    __half2 hv = __floats2half2_rn(acc[mt][n][rr * 2],
                                                   acc[mt][n][rr * 2 + 1]);
                    size_t off = base + (size_t)(r0 + rr * 8) * ldc + col;
                    *(__half2*)&Ch[off] = hv;
                }
            }
        }
    }
}

// ---------------- conversion kernels -----------------------------------------
__global__ void conv_half_kernel(const float* __restrict__ src,
                                 __half* __restrict__ dst, int n)
{
    int i = blockIdx.x * blockDim.x + threadIdx.x;
    if (i < n) dst[i] = __float2half(src[i]);
}

// W (K,N) fp32 row-major -> fp16 (N,K) row-major (transposed)
__global__ void conv_trans_h(const float* __restrict__ W,
                             __half* __restrict__ dst, int K, int N)
{
    __shared__ float t[32][33];
    int k0 = blockIdx.y * 32, n0 = blockIdx.x * 32;
    int tx = threadIdx.x, ty = threadIdx.y;
    #pragma unroll
    for (int r = ty; r < 32; r += 8)
        t[r][tx] = W[(size_t)(k0 + r) * N + n0 + tx];
    __syncthreads();
    #pragma unroll
    for (int r = ty; r < 32; r += 8)
        dst[(size_t)(n0 + r) * K + k0 + tx] = __float2half(t[tx][r]);
}

// ---------------- qkv split + RoPE -> fp16 q, k, transposed v ----------------
__global__ __launch_bounds__(256)
void rope_split_kernel(const float* __restrict__ qkv,
                       __half* __restrict__ qh, __half* __restrict__ kh,
                       __half* __restrict__ vTh)
{
    __shared__ float sv[32][65];
    int bid = blockIdx.x;
    int l0 = (bid & 31) * 32;
    int h = (bid >> 5) & 15;
    int b = bid >> 9;
    int tid = threadIdx.x;

    #pragma unroll
    for (int e = 0; e < 8; e++) {
        int idx = tid + e * 256;
        int d = idx & 63, lr = idx >> 6;
        int l = l0 + lr;
        long long base = ((long long)(b * Lq + l) * 3) * (Hq * Dq) + h * Dq;
        float qa = qkv[base + d];
        float ka = qkv[base + Hq * Dq + d];
        float vv = qkv[base + 2 * Hq * Dq + d];
        int dp = (d < 32) ? d + 32 : d - 32;
        float qb = qkv[base + dp];
        float kb = qkv[base + Hq * Dq + dp];

        int fi = (d < 32) ? d : d - 32;
        float ang = (float)l * powf(10000.0f, -(float)fi / 32.0f);
        float c = cosf(ang), s = sinf(ang);
        float sgn = (d < 32) ? -1.0f : 1.0f;

        float qv = qa * c + sgn * qb * s;
        float kv = ka * c + sgn * kb * s;

        long long o = ((long long)(b * Hq + h) * Lq + l) * Dq + d;
        qh[o] = __float2half(qv);
        kh[o] = __float2half(kv);
        sv[lr][d] = vv;
    }
    __syncthreads();
    #pragma unroll
    for (int e = 0; e < 8; e++) {
        int idx = tid + e * 256;
        int lr = idx & 31, d = idx >> 5;
        long long o = ((long long)(b * Hq + h) * Dq + d) * Lq + l0 + lr;
        vTh[o] = __float2half(sv[lr][d]);
    }
}

// ---------------- DAPE tables: kc[o][dist], ktab[h][dist] --------------------
__global__ void dape_pre_kernel(const float* __restrict__ w1, const float* __restrict__ b1,
                                const float* __restrict__ log_p, const float* __restrict__ log_a,
                                float* __restrict__ kc_t, float* __restrict__ ktab_t)
{
    int dist = blockIdx.x;
    int t = threadIdx.x;    // 32
    __shared__ float kv[16];
    if (t < 16) {
        float p = log1pf(expf(log_p[t]));
        float a = log1pf(expf(log_a[t]));
        float kvv = -p * log1pf(a * (float)dist);
        kv[t] = kvv;
        ktab_t[t * 1024 + dist] = kvv;
    }
    __syncthreads();
    float acc = b1[t];
    #pragma unroll
    for (int h = 0; h < 16; h++) acc += kv[h] * w1[(16 + h) * 32 + t];
    kc_t[t * 1024 + dist] = acc;
}

// ---------------- fused DAPE MLP + kerple + causal softmax (f32x2) ----------
__global__ __launch_bounds__(1024, 1)
void dape_softmax_kernel(const __half* __restrict__ scores,
                         __half* __restrict__ wh,
                         const float* __restrict__ w1, const float* __restrict__ w2,
                         const float* __restrict__ b2,
                         const float* __restrict__ kc_t, const float* __restrict__ ktab_t)
{
    __shared__ ull s_w1p[32 * 8];
    __shared__ ull s_w2p[32 * 8];
    __shared__ float s_b2[16];
    __shared__ float s_red[16 * 32];
    __shared__ float s_bc[16];

    int tid = threadIdx.x;
    int i = blockIdx.x & (Lq - 1);
    int b = blockIdx.x >> 10;

    if (tid < 256) {
        int o = tid >> 3, p = tid & 7;
        s_w1p[o * 8 + p] = pk2(w1[(2 * p) * 32 + o], w1[(2 * p + 1) * 32 + o]);
        s_w2p[o * 8 + p] = pk2(w2[o * 16 + 2 * p], w2[o * 16 + 2 * p + 1]);
    }
    if (tid < 16) s_b2[tid] = b2[tid];
    __syncthreads();

    long long base0 = (long long)b * (Hq * Lq * Lq) + (long long)i * Lq;
    int j = tid;
    ull out2[8];

    if (j <= i) {
        int dist = i - j;
        ull s2[8];
        #pragma unroll
        for (int p = 0; p < 8; p++) {
            float s0 = __half2float(scores[base0 + (long long)(2 * p)     * (Lq * Lq) + j]);
            float s1 = __half2float(scores[base0 + (long long)(2 * p + 1) * (Lq * Lq) + j]);
            s2[p] = pk2(s0, s1);
            float k0 = ktab_t[(2 * p) * 1024 + dist];
            float k1 = ktab_t[(2 * p + 1) * 1024 + dist];
            out2[p] = pk2(s0 + k0 + s_b2[2 * p], s1 + k1 + s_b2[2 * p + 1]);
        }
        #pragma unroll 4
        for (int o = 0; o < 32; o++) {
            ull acc2 = pk2(kc_t[o * 1024 + dist], 0.0f);
            #pragma unroll
            for (int p = 0; p < 8; p++) acc2 = ffma2(s2[p], s_w1p[o * 8 + p], acc2);
            float a0, a1; upk2(acc2, a0, a1);
            float acc = a0 + a1;
            float u = 0.7978845608f * (acc + 0.044715f * acc * acc * acc);
            float th; asm("tanh.approx.f32 %0,%1;" : "=f"(th) : "f"(u));
            float g = 0.5f * acc * (1.0f + th);
            ull g2 = pk2(g, g);
            #pragma unroll
            for (int p = 0; p < 8; p++) out2[p] = ffma2(g2, s_w2p[o * 8 + p], out2[p]);
        }
    } else {
        #pragma unroll
        for (int p = 0; p < 8; p++) out2[p] = pk2(-INFINITY, -INFINITY);
    }

    int warp = tid >> 5, ln = tid & 31;

    #pragma unroll
    for (int p = 0; p < 8; p++) {
        float v0, v1; upk2(out2[p], v0, v1);
        #pragma unroll
        for (int off = 16; off > 0; off >>= 1) {
            v0 = fmaxf(v0, __shfl_xor_sync(0xffffffffu, v0, off));
            v1 = fmaxf(v1, __shfl_xor_sync(0xffffffffu, v1, off));
        }
        if (ln == 0) { s_red[(2 * p) * 32 + warp] = v0; s_red[(2 * p + 1) * 32 + warp] = v1; }
    }
    __syncthreads();
    if (tid < 16) {
        float v = s_red[tid * 32];
        #pragma unroll
        for (int w = 1; w < 32; w++) v = fmaxf(v, s_red[tid * 32 + w]);
        s_bc[tid] = v;
    }
    __syncthreads();

    #pragma unroll
    for (int p = 0; p < 8; p++) {
        float v0, v1; upk2(out2[p], v0, v1);
        v0 = __expf(v0 - s_bc[2 * p]);
        v1 = __expf(v1 - s_bc[2 * p + 1]);
        out2[p] = pk2(v0, v1);
    }
    __syncthreads();
    #pragma unroll
    for (int p = 0; p < 8; p++) {
        float v0, v1; upk2(out2[p], v0, v1);
        #pragma unroll
        for (int off = 16; off > 0; off >>= 1) {
            v0 += __shfl_xor_sync(0xffffffffu, v0, off);
            v1 += __shfl_xor_sync(0xffffffffu, v1, off);
        }
        if (ln == 0) { s_red[(2 * p) * 32 + warp] = v0; s_red[(2 * p + 1) * 32 + warp] = v1; }
    }
    __syncthreads();
    if (tid < 16) {
        float v = 0.0f;
        #pragma unroll
        for (int w = 0; w < 32; w++) v += s_red[tid * 32 + w];
        s_bc[tid] = 1.0f / v;
    }
    __syncthreads();

    #pragma unroll
    for (int p = 0; p < 8; p++) {
        float v0, v1; upk2(out2[p], v0, v1);
        long long off0 = base0 + (long long)(2 * p) * (Lq * Lq) + j;
        long long off1 = base0 + (long long)(2 * p + 1) * (Lq * Lq) + j;
        wh[off0] = __float2half(v0 * s_bc[2 * p]);
        wh[off1] = __float2half(v1 * s_bc[2 * p + 1]);
    }
}

// ---------------- launch ----------------------------------------------------
extern "C" void kernel_launch(void* const* d_in, const int* in_sizes, int n_in,
                              void* d_out, int out_size)
{
    const float* x     = (const float*)d_in[0];
    const float* w_qkv = (const float*)d_in[1];
    const float* w_o   = (const float*)d_in[2];
    const float* log_p = (const float*)d_in[3];
    const float* log_a = (const float*)d_in[4];
    const float* w1    = (const float*)d_in[5];
    const float* b1    = (const float*)d_in[6];
    const float* w2    = (const float*)d_in[7];
    const float* b2    = (const float*)d_in[8];
    float* out = (float*)d_out;
    (void)in_sizes; (void)n_in; (void)out_size;

    float *qkv, *kc, *ktab;
    __half *sch, *qh, *kh, *vTh, *wh;
    __half *xh, *wqT, *attnh, *woT;
    cudaGetSymbolAddress((void**)&qkv,  g_qkv);
    cudaGetSymbolAddress((void**)&sch,  g_sch);
    cudaGetSymbolAddress((void**)&kc,   g_kc);
    cudaGetSymbolAddress((void**)&ktab, g_ktab);
    cudaGetSymbolAddress((void**)&qh,   g_qh);
    cudaGetSymbolAddress((void**)&kh,   g_kh);
    cudaGetSymbolAddress((void**)&vTh,  g_vTh);
    cudaGetSymbolAddress((void**)&wh,   g_wh);
    cudaGetSymbolAddress((void**)&xh,    g_xh);
    cudaGetSymbolAddress((void**)&wqT,   g_wqkvTh);
    cudaGetSymbolAddress((void**)&attnh, g_attnh);
    cudaGetSymbolAddress((void**)&woT,   g_woTh);

    const int SM_DENSE  = 4 * 16384;   // <128, NSTG=4>
    const int SM_SCORES = 3 * 16384;   // <128, NSTG=3>
    const int SM_AV     = 3 * 12288;   // <64,  NSTG=3>

    static int smem_set = 0;
    if (!smem_set) {
        cudaFuncSetAttribute(hgemm_kernel<128, 4, 0, 0, 0>,
                             cudaFuncAttributeMaxDynamicSharedMemorySize, SM_DENSE);
        cudaFuncSetAttribute(hgemm_kernel<128, 3, 1, 0, 2>,
                             cudaFuncAttributeMaxDynamicSharedMemorySize, SM_SCORES);
        cudaFuncSetAttribute(hgemm_kernel<64, 3, 0, 1, 1>,
                             cudaFuncAttributeMaxDynamicSharedMemorySize, SM_AV);
        smem_set = 1;
    }

    const int M = Bq * Lq;           // 2048
    const int TH = 3 * Hq * Dq;      // 3072

    // 0) DAPE tables
    dape_pre_kernel<<<1024, 32>>>(w1, b1, log_p, log_a, kc, ktab);

    // 1) conversions for qkv GEMM (x fp16; w_qkv^T fp16)
    conv_half_kernel<<<(M * HIDq) / 256, 256>>>(x, xh, M * HIDq);
    conv_trans_h<<<dim3(TH / 32, HIDq / 32), dim3(32, 8)>>>(w_qkv, wqT, HIDq, TH);

    // 2) qkv = x @ w_qkv (fp16 single-pass, 4-stage)
    hgemm_kernel<128, 4, 0, 0, 0><<<dim3(TH / 128, M / 128), 256, SM_DENSE>>>(
        xh, wqT, qkv, nullptr,
        M, TH, HIDq, HIDq, HIDq, TH, 0, 0, 0, 1.0f);

    // 3) split + RoPE -> fp16 q, k, transposed v
    rope_split_kernel<<<Bq * Hq * (Lq / 32), 256>>>(qkv, qh, kh, vTh);

    // 4) scores = (q @ k^T)/8, batched 32, causal tile skip -> fp16 planes
    hgemm_kernel<128, 3, 1, 0, 2><<<dim3(Lq / 128, Lq / 128, Bq * Hq), 256, SM_SCORES>>>(
        qh, kh, nullptr, sch,
        Lq, Lq, Dq, Dq, Dq, Lq,
        (long long)Lq * Dq, (long long)Lq * Dq, (long long)Lq * Lq, 0.125f);

    // 5) fused kerple + DAPE MLP + causal softmax -> fp16 weights
    dape_softmax_kernel<<<Bq * Lq, 1024>>>(sch, wh, w1, w2, b2, kc, ktab);

    // 6) attn = weights @ v (fp16 single-pass, causal-K, fp16 out in (B,L,H*D))
    hgemm_kernel<64, 3, 0, 1, 1><<<dim3(1, Lq / 128, Bq * Hq), 256, SM_AV>>>(
        wh, vTh, nullptr, attnh,
        Lq, Dq, Lq, Lq, Lq, HIDq,
        (long long)Lq * Lq, (long long)Dq * Lq, 0, 1.0f);

    // 7) out = attn @ w_o (fp16 single-pass, 4-stage)
    conv_trans_h<<<dim3(HIDq / 32, HIDq / 32), dim3(32, 8)>>>(w_o, woT, HIDq, HIDq);
    hgemm_kernel<128, 4, 0, 0, 0><<<dim3(HIDq / 128, M / 128), 256, SM_DENSE>>>(
        attnh, woT, out, nullptr,
        M, HIDq, HIDq, HIDq, HIDq, HIDq, 0, 0, 0, 1.0f);
}